// round 11
// baseline (speedup 1.0000x reference)
#include <cuda_runtime.h>
#include <cuda_fp16.h>
#include <stdint.h>

// ---------------- problem constants ----------------
#define EDGES   524288
#define NNODES  16384
#define HD      256
#define EIN     512
#define DD      1024

// ---------------- device scratch (no allocations allowed) ----------------
static __device__ int    g_idx64;
static __device__ __half g_WT[1835008];                   // all weights, [N][K] fp16
static __device__ __half g_Xa[(size_t)EDGES * HD];
static __device__ __half g_Xb[(size_t)EDGES * HD];
static __device__ float  g_h [(size_t)NNODES * HD];       // post-LN1 h (fp32 residual)
static __device__ __half g_hh[(size_t)NNODES * HD];       // post-LN1 h (fp16)
// CSR structures
static __device__ int    g_cnt[NNODES];
static __device__ int    g_off[NNODES + 1];
static __device__ int    g_cur[NNODES];
static __device__ int    g_elist[EDGES];

#define WOFF_M0 0         // [256][512]
#define WOFF_M1 131072    // [256][256]
#define WOFF_M2 196608    // [256][256]
#define WOFF_D0 262144    // [1024][256]
#define WOFF_D1 524288    // [1024][1024]
#define WOFF_D2 1572864   // [256][1024]

// ---------------- helpers ----------------
__device__ __forceinline__ float gelu_f(float x) {
    return 0.5f * x * (1.0f + erff(x * 0.70710678118654752f));
}
__device__ __forceinline__ void cpasync16(uint32_t dst, const void* src) {
    asm volatile("cp.async.cg.shared.global [%0], [%1], 16;" :: "r"(dst), "l"(src) : "memory");
}
__device__ __forceinline__ void cp_commit() {
    asm volatile("cp.async.commit_group;" ::: "memory");
}
__device__ __forceinline__ void ldsm4(uint32_t* r, uint32_t addr) {
    asm volatile("ldmatrix.sync.aligned.m8n8.x4.shared.b16 {%0,%1,%2,%3}, [%4];"
                 : "=r"(r[0]), "=r"(r[1]), "=r"(r[2]), "=r"(r[3]) : "r"(addr));
}
__device__ __forceinline__ void mma16816(float* c, const uint32_t* a, const uint32_t* b) {
    asm volatile("mma.sync.aligned.m16n8k16.row.col.f32.f16.f16.f32 "
                 "{%0,%1,%2,%3}, {%4,%5,%6,%7}, {%8,%9}, {%0,%1,%2,%3};"
                 : "+f"(c[0]), "+f"(c[1]), "+f"(c[2]), "+f"(c[3])
                 : "r"(a[0]), "r"(a[1]), "r"(a[2]), "r"(a[3]), "r"(b[0]), "r"(b[1]));
}

// ---------------- prep kernels ----------------
__global__ void detect_idx_kernel(const int* p) {
    if (threadIdx.x == 0 && blockIdx.x == 0) {
        int is64 = 1;
        for (int i = 1; i < 512; i += 2)
            if (p[i] != 0) { is64 = 0; break; }
        g_idx64 = is64;
    }
}

// W [K,N] fp32 row-major -> WT [N,K] fp16 row-major
__global__ void prep_wt_kernel(const float* __restrict__ W, __half* __restrict__ WT, int K, int N) {
    long long idx = (long long)blockIdx.x * blockDim.x + threadIdx.x;
    if (idx >= (long long)K * N) return;
    int k = (int)(idx / N);
    int n = (int)(idx % N);
    WT[(long long)n * K + k] = __float2half(W[idx]);
}

// ---------------- CSR build ----------------
__global__ void zero_cnt_kernel() {
    int i = blockIdx.x * 256 + threadIdx.x;
    if (i < NNODES) g_cnt[i] = 0;
}
__global__ void count_kernel(const void* __restrict__ eidx) {
    int e = blockIdx.x * 256 + threadIdx.x;
    int n = g_idx64 ? (int)((const long long*)eidx)[e] : ((const int*)eidx)[e];
    atomicAdd(&g_cnt[n], 1);
}
__global__ void scan_kernel() {
    __shared__ int part[1024];
    int t = threadIdx.x;
    int loc[16]; int s = 0;
#pragma unroll
    for (int i = 0; i < 16; i++) { loc[i] = g_cnt[t * 16 + i]; s += loc[i]; }
    part[t] = s;
    __syncthreads();
    for (int o = 1; o < 1024; o <<= 1) {
        int v = (t >= o) ? part[t - o] : 0;
        __syncthreads();
        part[t] += v;
        __syncthreads();
    }
    int run = (t == 0) ? 0 : part[t - 1];
#pragma unroll
    for (int i = 0; i < 16; i++) { g_off[t * 16 + i] = run; g_cur[t * 16 + i] = run; run += loc[i]; }
    if (t == 1023) g_off[NNODES] = run;
}
__global__ void fill_kernel(const void* __restrict__ eidx) {
    int e = blockIdx.x * 256 + threadIdx.x;
    int n = g_idx64 ? (int)((const long long*)eidx)[e] : ((const int*)eidx)[e];
    int pos = atomicAdd(&g_cur[n], 1);
    g_elist[pos] = e;
}

// ---------------- fused gather + LN1 ----------------
__global__ void gather_ln1_kernel(const __half* __restrict__ m,
                                  const float* __restrict__ hV,
                                  const float* __restrict__ g1, const float* __restrict__ b1,
                                  float* __restrict__ h, __half* __restrict__ hh) {
    __shared__ float sm1[8], sm2[8];
    const int n = blockIdx.x, c = threadIdx.x;
    const int wid = c >> 5, lane = c & 31;
    const int s = g_off[n], e = g_off[n + 1];
    float acc = 0.f;
    int i = s;
    for (; i + 4 <= e; i += 4) {
        int e0 = g_elist[i], e1 = g_elist[i + 1], e2 = g_elist[i + 2], e3 = g_elist[i + 3];
        acc += __half2float(m[(size_t)e0 * HD + c]);
        acc += __half2float(m[(size_t)e1 * HD + c]);
        acc += __half2float(m[(size_t)e2 * HD + c]);
        acc += __half2float(m[(size_t)e3 * HD + c]);
    }
    for (; i < e; i++)
        acc += __half2float(m[(size_t)g_elist[i] * HD + c]);

    const float v = hV[(size_t)n * HD + c] + acc * (1.0f / 30.0f);
    float s1 = v, s2 = v * v;
#pragma unroll
    for (int off = 16; off; off >>= 1) {
        s1 += __shfl_xor_sync(0xffffffffu, s1, off);
        s2 += __shfl_xor_sync(0xffffffffu, s2, off);
    }
    if (lane == 0) { sm1[wid] = s1; sm2[wid] = s2; }
    __syncthreads();
    float t1 = 0.f, t2 = 0.f;
#pragma unroll
    for (int k = 0; k < 8; k++) { t1 += sm1[k]; t2 += sm2[k]; }
    const float mu  = t1 * (1.0f / HD);
    const float var = t2 * (1.0f / HD) - mu * mu;
    const float rs  = rsqrtf(var + 1e-5f);
    const float y = (v - mu) * rs * g1[c] + b1[c];
    h [(size_t)n * HD + c] = y;
    hh[(size_t)n * HD + c] = __float2half(y);
}

// ---------------- GEMM tiling constants ----------------
#define BM 128
#define BK 64
#define ASTR 72                          // BK + 8 halfs: ldmatrix conflict-free
#define A_BYTES (BM * ASTR * 2)          // 18432 per stage
#define NSTAGE 3
// 512-thread / BN=256 shapes (fused23, LN2 kernel)
#define BN_BIG 256
#define BBIG_BYTES (BN_BIG * ASTR * 2)   // 36864 per stage
#define SMEM_BIG (NSTAGE * (A_BYTES + BBIG_BYTES))  // 165888
#define A2_OFF  0
#define B2_OFF  (4 * A_BYTES)
// 256-thread / BN=128 shape (main GELU gemms)
#define BN2 128
#define B2S_BYTES (BN2 * ASTR * 2)       // 18432 per stage
#define SMEM_256 (NSTAGE * (A_BYTES + B2S_BYTES))   // 110592 -> 2 CTAs/SM

// ---------------- gemm256: 256 thr, BM=128 x BN=128, 2 CTAs/SM ----------------
// grid: x = n-tile, y = m-tile (adjacent bids share the A strip -> L2 hit)
template <int K, bool AF32>
__global__ void __launch_bounds__(256, 2)
gemm256(const void* __restrict__ Ain, const __half* __restrict__ WT_full,
        const float* __restrict__ bias_full,
        __half* __restrict__ out, int ldout) {
    extern __shared__ char smem[];
    __half* As = (__half*)smem;
    const int tid = threadIdx.x;
    const int n0g = blockIdx.x * BN2;
    const int m0  = blockIdx.y * BM;
    const __half* WT  = WT_full + (size_t)n0g * K;
    const float* bias = bias_full + n0g;
    const __half* Ah  = (const __half*)Ain;
    const float*  Af  = (const float*)Ain;

    const uint32_t sA = (uint32_t)__cvta_generic_to_shared(smem);
    const uint32_t sB = sA + NSTAGE * A_BYTES;

    const int lane = tid & 31, warp = tid >> 5;
    const int wm = warp & 3, wn = warp >> 2;      // 4 m-warps x 2 n-warps; warp tile 32x64
    const int ml = lane & 7, tl = lane >> 3;

    // hoisted ldsm base offsets (bytes, without slot/k offsets)
    const uint32_t aBase = sA + (uint32_t)(((wm * 32 + ml + (tl & 1) * 8) * ASTR + (tl >> 1) * 8) * 2);
    const uint32_t bBase = sB + (uint32_t)(((wn * 64 + ml + (tl >> 1) * 8) * ASTR + (tl & 1) * 8) * 2);

    // producers: A 1024 chunks/stage, B 1024 chunks/stage -> 4 per thread each
    float4 ra[4][2];
    auto ldgA = [&](int kc) {
        if constexpr (AF32) {
#pragma unroll
            for (int i = 0; i < 4; i++) {
                int idx = tid + i * 256;
                int r = idx >> 3, q = idx & 7;
                const float4* p = (const float4*)(Af + (size_t)(m0 + r) * K + kc * BK + q * 8);
                ra[i][0] = p[0];
                ra[i][1] = p[1];
            }
        }
    };
    auto stsA = [&](int slot) {
        if constexpr (AF32) {
#pragma unroll
            for (int i = 0; i < 4; i++) {
                int idx = tid + i * 256;
                int r = idx >> 3, q = idx & 7;
                alignas(16) __half2 hv[4];
                hv[0] = __floats2half2_rn(ra[i][0].x, ra[i][0].y);
                hv[1] = __floats2half2_rn(ra[i][0].z, ra[i][0].w);
                hv[2] = __floats2half2_rn(ra[i][1].x, ra[i][1].y);
                hv[3] = __floats2half2_rn(ra[i][1].z, ra[i][1].w);
                *(uint4*)(As + slot * (A_BYTES / 2) + r * ASTR + q * 8) = *(uint4*)hv;
            }
        }
    };
    auto issueB = [&](int kc, int slot) {
        if constexpr (!AF32) {
#pragma unroll
            for (int i = 0; i < 4; i++) {
                int idx = tid + i * 256;
                int r = idx >> 3, q = idx & 7;
                cpasync16(sA + slot * A_BYTES + (uint32_t)((r * ASTR + q * 8) * 2),
                          Ah + (size_t)(m0 + r) * K + kc * BK + q * 8);
            }
        }
#pragma unroll
        for (int i = 0; i < 4; i++) {
            int idx = tid + i * 256;
            int r = idx >> 3, q = idx & 7;
            cpasync16(sB + slot * B2S_BYTES + (uint32_t)((r * ASTR + q * 8) * 2),
                      WT + (size_t)r * K + kc * BK + q * 8);
        }
        cp_commit();
    };

    float acc[2][8][4];
#pragma unroll
    for (int mi = 0; mi < 2; mi++)
#pragma unroll
        for (int nj = 0; nj < 8; nj++)
#pragma unroll
            for (int j = 0; j < 4; j++) acc[mi][nj][j] = 0.f;

    const int NC = K / BK;
    ldgA(0); stsA(0); issueB(0, 0);
    ldgA(1); stsA(1); issueB(1, 1);
    ldgA(2);

    for (int c = 0; c < NC; c++) {
        const int slot = c % NSTAGE;
        if (c + 1 < NC) asm volatile("cp.async.wait_group 1;" ::: "memory");
        else            asm volatile("cp.async.wait_group 0;" ::: "memory");
        __syncthreads();
        if (c + 2 < NC) {
            stsA((c + 2) % NSTAGE);
            issueB(c + 2, (c + 2) % NSTAGE);
            if (c + 3 < NC) ldgA(c + 3);
        }

        const uint32_t aS = aBase + slot * A_BYTES;
        const uint32_t bS = bBase + slot * B2S_BYTES;
#pragma unroll
        for (int ks = 0; ks < 4; ks++) {
            const uint32_t kb = (uint32_t)(ks * 16 * 2);
            uint32_t afr[2][4];
#pragma unroll
            for (int mi = 0; mi < 2; mi++)
                ldsm4(afr[mi], aS + kb + (uint32_t)(mi * 16 * ASTR * 2));
#pragma unroll
            for (int jj = 0; jj < 4; jj++) {
                uint32_t bfr[4];
                ldsm4(bfr, bS + kb + (uint32_t)(jj * 16 * ASTR * 2));
#pragma unroll
                for (int mi = 0; mi < 2; mi++) {
                    mma16816(acc[mi][2 * jj],     afr[mi], bfr);
                    mma16816(acc[mi][2 * jj + 1], afr[mi], bfr + 2);
                }
            }
        }
    }

    // epilogue: gelu(acc + bias) -> fp16
    const int g  = lane >> 2;
    const int t2 = (lane & 3) * 2;
#pragma unroll
    for (int mi = 0; mi < 2; mi++) {
        const int r0 = wm * 32 + mi * 16 + g;
#pragma unroll
        for (int nj = 0; nj < 8; nj++) {
            const int col = wn * 64 + nj * 8 + t2;
            const float b0v = bias[col], b1v = bias[col + 1];
            float x0 = gelu_f(acc[mi][nj][0] + b0v);
            float x1 = gelu_f(acc[mi][nj][1] + b1v);
            *(__half2*)(out + (size_t)(m0 + r0) * ldout + n0g + col) = __floats2half2_rn(x0, x1);
            float x2 = gelu_f(acc[mi][nj][2] + b0v);
            float x3 = gelu_f(acc[mi][nj][3] + b1v);
            *(__half2*)(out + (size_t)(m0 + r0 + 8) * ldout + n0g + col) = __floats2half2_rn(x2, x3);
        }
    }
}

// ---------------- final GEMM + LN2 (512 thr, BN=256, K=1024) ----------------
__global__ void __launch_bounds__(512, 1)
gemm_ln2(const __half* __restrict__ Ah, const __half* __restrict__ WT,
         const float* __restrict__ bias,
         const float* __restrict__ h_res, const float* __restrict__ ln_g,
         const float* __restrict__ ln_b, float* __restrict__ outf) {
    constexpr int K = 1024;
    extern __shared__ char smem[];
    const int tid = threadIdx.x;
    const int m0  = blockIdx.x * BM;

    const uint32_t sA = (uint32_t)__cvta_generic_to_shared(smem);
    const uint32_t sB = sA + NSTAGE * A_BYTES;

    const int lane = tid & 31, warp = tid >> 5;
    const int wm = warp & 3, wn = warp >> 2;
    const int ml = lane & 7, tl = lane >> 3;

    auto issue = [&](int kc, int slot) {
#pragma unroll
        for (int i = 0; i < 2; i++) {
            int idx = tid + i * 512;
            int r = idx >> 3, q = idx & 7;
            cpasync16(sA + slot * A_BYTES + (uint32_t)((r * ASTR + q * 8) * 2),
                      Ah + (size_t)(m0 + r) * K + kc * BK + q * 8);
        }
#pragma unroll
        for (int i = 0; i < 4; i++) {
            int idx = tid + i * 512;
            int r = idx >> 3, q = idx & 7;
            cpasync16(sB + slot * BBIG_BYTES + (uint32_t)((r * ASTR + q * 8) * 2),
                      WT + (size_t)r * K + kc * BK + q * 8);
        }
        cp_commit();
    };

    float acc[2][8][4];
#pragma unroll
    for (int mi = 0; mi < 2; mi++)
#pragma unroll
        for (int nj = 0; nj < 8; nj++)
#pragma unroll
            for (int j = 0; j < 4; j++) acc[mi][nj][j] = 0.f;

    const int NC = K / BK;
    issue(0, 0);
    issue(1, 1);
    for (int c = 0; c < NC; c++) {
        const int slot = c % NSTAGE;
        if (c + 1 < NC) asm volatile("cp.async.wait_group 1;" ::: "memory");
        else            asm volatile("cp.async.wait_group 0;" ::: "memory");
        __syncthreads();
        if (c + 2 < NC) issue(c + 2, (c + 2) % NSTAGE);

        const uint32_t aB = sA + slot * A_BYTES;
        const uint32_t bB = sB + slot * BBIG_BYTES;
#pragma unroll
        for (int ks = 0; ks < 4; ks++) {
            const int kofs = ks * 16;
            uint32_t afr[2][4];
#pragma unroll
            for (int mi = 0; mi < 2; mi++) {
                int row = wm * 32 + mi * 16 + ml + (tl & 1) * 8;
                int col = kofs + (tl >> 1) * 8;
                ldsm4(afr[mi], aB + (uint32_t)((row * ASTR + col) * 2));
            }
#pragma unroll
            for (int jj = 0; jj < 4; jj++) {
                uint32_t bfr[4];
                int rn  = wn * 64 + jj * 16 + ml + (tl >> 1) * 8;
                int col = kofs + (tl & 1) * 8;
                ldsm4(bfr, bB + (uint32_t)((rn * ASTR + col) * 2));
#pragma unroll
                for (int mi = 0; mi < 2; mi++) {
                    mma16816(acc[mi][2 * jj],     afr[mi], bfr);
                    mma16816(acc[mi][2 * jj + 1], afr[mi], bfr + 2);
                }
            }
        }
    }

    // LN2 epilogue
    __syncthreads();
    float* sb = (float*)smem;
    const int g  = lane >> 2;
    const int t2 = (lane & 3) * 2;
#pragma unroll
    for (int mi = 0; mi < 2; mi++) {
        const int r0 = wm * 32 + mi * 16 + g;
#pragma unroll
        for (int nj = 0; nj < 8; nj++) {
            const int col = wn * 64 + nj * 8 + t2;
            const float b0v = bias[col], b1v = bias[col + 1];
            sb[r0 * 264 + col]           = acc[mi][nj][0] + b0v + h_res[(size_t)(m0 + r0) * HD + col];
            sb[r0 * 264 + col + 1]       = acc[mi][nj][1] + b1v + h_res[(size_t)(m0 + r0) * HD + col + 1];
            sb[(r0 + 8) * 264 + col]     = acc[mi][nj][2] + b0v + h_res[(size_t)(m0 + r0 + 8) * HD + col];
            sb[(r0 + 8) * 264 + col + 1] = acc[mi][nj][3] + b1v + h_res[(size_t)(m0 + r0 + 8) * HD + col + 1];
        }
    }
    __syncthreads();
    for (int rr = 0; rr < 8; rr++) {
        const int row = warp * 8 + rr;
        float s = 0.f, s2 = 0.f;
#pragma unroll
        for (int i = 0; i < 8; i++) {
            float v = sb[row * 264 + lane + i * 32];
            s += v; s2 += v * v;
        }
#pragma unroll
        for (int off = 16; off; off >>= 1) {
            s  += __shfl_xor_sync(0xffffffffu, s, off);
            s2 += __shfl_xor_sync(0xffffffffu, s2, off);
        }
        const float mu  = s * (1.0f / HD);
        const float var = s2 * (1.0f / HD) - mu * mu;
        const float rs  = rsqrtf(var + 1e-5f);
#pragma unroll
        for (int i = 0; i < 8; i++) {
            const int cc = lane + i * 32;
            const float v = sb[row * 264 + cc];
            outf[(size_t)(m0 + row) * HD + cc] = (v - mu) * rs * ln_g[cc] + ln_b[cc];
        }
    }
}

// ---------------- fused edge GEMM2+GEMM3 (512 thr, BN=256) ----------------
__global__ void __launch_bounds__(512, 1)
gemm_fused23(const __half* __restrict__ Xin,
             const __half* __restrict__ W1, const float* __restrict__ b1,
             const __half* __restrict__ W2, const float* __restrict__ b2,
             __half* __restrict__ out) {
    extern __shared__ char smem[];
    __half* As2 = (__half*)smem;
    const int tid = threadIdx.x;
    const int m0  = blockIdx.x * BM;

    const uint32_t sA  = (uint32_t)__cvta_generic_to_shared(smem);
    const uint32_t sB  = sA + NSTAGE * A_BYTES;
    const uint32_t sA2 = sA + A2_OFF;
    const uint32_t sB2 = sA + B2_OFF;

    const int lane = tid & 31, warp = tid >> 5;
    const int wm = warp & 3, wn = warp >> 2;
    const int ml = lane & 7, tl = lane >> 3;

    auto issue1 = [&](int kc, int slot) {
#pragma unroll
        for (int i = 0; i < 2; i++) {
            int idx = tid + i * 512;
            int r = idx >> 3, q = idx & 7;
            cpasync16(sA + slot * A_BYTES + (uint32_t)((r * ASTR + q * 8) * 2),
                      Xin + (size_t)(m0 + r) * 256 + kc * BK + q * 8);
        }
#pragma unroll
        for (int i = 0; i < 4; i++) {
            int idx = tid + i * 512;
            int r = idx >> 3, q = idx & 7;
            cpasync16(sB + slot * BBIG_BYTES + (uint32_t)((r * ASTR + q * 8) * 2),
                      W1 + (size_t)r * 256 + kc * BK + q * 8);
        }
        cp_commit();
    };
    auto issue2 = [&](int kc, int slot) {
#pragma unroll
        for (int i = 0; i < 4; i++) {
            int idx = tid + i * 512;
            int r = idx >> 3, q = idx & 7;
            cpasync16(sB2 + slot * BBIG_BYTES + (uint32_t)((r * ASTR + q * 8) * 2),
                      W2 + (size_t)r * 256 + kc * BK + q * 8);
        }
        cp_commit();
    };

    float acc[2][8][4];
#pragma unroll
    for (int mi = 0; mi < 2; mi++)
#pragma unroll
        for (int nj = 0; nj < 8; nj++)
#pragma unroll
            for (int j = 0; j < 4; j++) acc[mi][nj][j] = 0.f;

    issue1(0, 0);
    issue1(1, 1);
    for (int c = 0; c < 4; c++) {
        const int slot = c % NSTAGE;
        if (c + 1 < 4) asm volatile("cp.async.wait_group 1;" ::: "memory");
        else           asm volatile("cp.async.wait_group 0;" ::: "memory");
        __syncthreads();
        if (c + 2 < 4) issue1(c + 2, (c + 2) % NSTAGE);

        const uint32_t aB = sA + slot * A_BYTES;
        const uint32_t bB = sB + slot * BBIG_BYTES;
#pragma unroll
        for (int ks = 0; ks < 4; ks++) {
            const int kofs = ks * 16;
            uint32_t afr[2][4];
#pragma unroll
            for (int mi = 0; mi < 2; mi++) {
                int row = wm * 32 + mi * 16 + ml + (tl & 1) * 8;
                int col = kofs + (tl >> 1) * 8;
                ldsm4(afr[mi], aB + (uint32_t)((row * ASTR + col) * 2));
            }
#pragma unroll
            for (int jj = 0; jj < 4; jj++) {
                uint32_t bfr[4];
                int rn  = wn * 64 + jj * 16 + ml + (tl >> 1) * 8;
                int col = kofs + (tl & 1) * 8;
                ldsm4(bfr, bB + (uint32_t)((rn * ASTR + col) * 2));
#pragma unroll
                for (int mi = 0; mi < 2; mi++) {
                    mma16816(acc[mi][2 * jj],     afr[mi], bfr);
                    mma16816(acc[mi][2 * jj + 1], afr[mi], bfr + 2);
                }
            }
        }
    }

    __syncthreads();
    {
        const int g  = lane >> 2;
        const int t2 = (lane & 3) * 2;
#pragma unroll
        for (int mi = 0; mi < 2; mi++) {
            const int r0 = wm * 32 + mi * 16 + g;
#pragma unroll
            for (int nj = 0; nj < 8; nj++) {
                const int cl  = nj * 8 + t2;
                const int col = wn * 64 + cl;
                const float b0v = b1[col], b1v = b1[col + 1];
                __half2 v01 = __floats2half2_rn(gelu_f(acc[mi][nj][0] + b0v),
                                                gelu_f(acc[mi][nj][1] + b1v));
                __half2 v23 = __floats2half2_rn(gelu_f(acc[mi][nj][2] + b0v),
                                                gelu_f(acc[mi][nj][3] + b1v));
                *(__half2*)(As2 + wn * (A_BYTES / 2) + r0 * ASTR + cl)       = v01;
                *(__half2*)(As2 + wn * (A_BYTES / 2) + (r0 + 8) * ASTR + cl) = v23;
                acc[mi][nj][0] = acc[mi][nj][1] = acc[mi][nj][2] = acc[mi][nj][3] = 0.f;
            }
        }
    }
    __syncthreads();
    issue2(0, 0);
    issue2(1, 1);

    for (int c = 0; c < 4; c++) {
        const int slot = c & 1;
        if (c + 1 < 4) asm volatile("cp.async.wait_group 1;" ::: "memory");
        else           asm volatile("cp.async.wait_group 0;" ::: "memory");
        __syncthreads();

        const uint32_t aB = sA2 + c * A_BYTES;
        const uint32_t bB = sB2 + slot * BBIG_BYTES;
#pragma unroll
        for (int ks = 0; ks < 4; ks++) {
            const int kofs = ks * 16;
            uint32_t afr[2][4];
#pragma unroll
            for (int mi = 0; mi < 2; mi++) {
                int row = wm * 32 + mi * 16 + ml + (tl & 1) * 8;
                int col = kofs + (tl >> 1) * 8;
                ldsm4(afr[mi], aB + (uint32_t)((row * ASTR + col) * 2));
            }
#pragma unroll
            for (int jj = 0; jj < 4; jj++) {
                uint32_t bfr[4];
                int rn  = wn * 64 + jj * 16 + ml + (tl >> 1) * 8;
                int col = kofs + (tl & 1) * 8;
                ldsm4(bfr, bB + (uint32_t)((rn * ASTR + col) * 2));
#pragma unroll
                for (int mi = 0; mi < 2; mi++) {
                    mma16816(acc[mi][2 * jj],     afr[mi], bfr);
                    mma16816(acc[mi][2 * jj + 1], afr[mi], bfr + 2);
                }
            }
        }
        __syncthreads();
        if (c + 2 < 4) issue2(c + 2, slot);
    }

    {
        const int g  = lane >> 2;
        const int t2 = (lane & 3) * 2;
#pragma unroll
        for (int mi = 0; mi < 2; mi++) {
            const int r0 = wm * 32 + mi * 16 + g;
#pragma unroll
            for (int nj = 0; nj < 8; nj++) {
                const int col = wn * 64 + nj * 8 + t2;
                const float b0v = b2[col], b1v = b2[col + 1];
                float x0 = gelu_f(acc[mi][nj][0] + b0v);
                float x1 = gelu_f(acc[mi][nj][1] + b1v);
                *(__half2*)(out + (size_t)(m0 + r0) * HD + col) = __floats2half2_rn(x0, x1);
                float x2 = gelu_f(acc[mi][nj][2] + b0v);
                float x3 = gelu_f(acc[mi][nj][3] + b1v);
                *(__half2*)(out + (size_t)(m0 + r0 + 8) * HD + col) = __floats2half2_rn(x2, x3);
            }
        }
    }
}

// ---------------- host launcher ----------------
extern "C" void kernel_launch(void* const* d_in, const int* in_sizes, int n_in,
                              void* d_out, int out_size) {
    const float* h_V  = (const float*)d_in[0];
    const float* h_E  = (const float*)d_in[1];
    const void*  eidx = d_in[2];
    const float* m0w  = (const float*)d_in[3];
    const float* m0b  = (const float*)d_in[4];
    const float* m1w  = (const float*)d_in[5];
    const float* m1b  = (const float*)d_in[6];
    const float* m2w  = (const float*)d_in[7];
    const float* m2b  = (const float*)d_in[8];
    const float* d0w  = (const float*)d_in[9];
    const float* d0b  = (const float*)d_in[10];
    const float* d1w  = (const float*)d_in[11];
    const float* d1b  = (const float*)d_in[12];
    const float* d2w  = (const float*)d_in[13];
    const float* d2b  = (const float*)d_in[14];
    const float* ln1g = (const float*)d_in[15];
    const float* ln1b = (const float*)d_in[16];
    const float* ln2g = (const float*)d_in[17];
    const float* ln2b = (const float*)d_in[18];
    float* outf = (float*)d_out;
    (void)n_in; (void)out_size; (void)in_sizes;

    void *pWT, *pXa, *pXb, *pH, *pHH;
    cudaGetSymbolAddress(&pWT, g_WT);
    cudaGetSymbolAddress(&pXa, g_Xa);
    cudaGetSymbolAddress(&pXb, g_Xb);
    cudaGetSymbolAddress(&pH,  g_h);
    cudaGetSymbolAddress(&pHH, g_hh);
    __half* WT = (__half*)pWT;
    __half* Xa = (__half*)pXa;
    __half* Xb = (__half*)pXb;
    float*  hb = (float*)pH;
    __half* hh = (__half*)pHH;

    cudaFuncSetAttribute(gemm256<512,  true>,  cudaFuncAttributeMaxDynamicSharedMemorySize, SMEM_256);
    cudaFuncSetAttribute(gemm256<256,  false>, cudaFuncAttributeMaxDynamicSharedMemorySize, SMEM_256);
    cudaFuncSetAttribute(gemm256<1024, false>, cudaFuncAttributeMaxDynamicSharedMemorySize, SMEM_256);
    cudaFuncSetAttribute(gemm_ln2,     cudaFuncAttributeMaxDynamicSharedMemorySize, SMEM_BIG);
    cudaFuncSetAttribute(gemm_fused23, cudaFuncAttributeMaxDynamicSharedMemorySize, SMEM_BIG);

    // --- launch order: GEMM1 is the 4th launch (ncu capture slot) ---
    detect_idx_kernel<<<1, 32>>>((const int*)eidx);                                // 1
    prep_wt_kernel<<<(512 * 256 + 255) / 256, 256>>>(m0w, WT + WOFF_M0, 512, 256); // 2
    zero_cnt_kernel<<<NNODES / 256, 256>>>();                                      // 3
    gemm256<512, true><<<dim3(2, EDGES / BM), 256, SMEM_256>>>(                    // 4 <- profiled
        h_E, WT + WOFF_M0, m0b, Xa, HD);

    count_kernel<<<EDGES / 256, 256>>>(eidx);
    scan_kernel<<<1, 1024>>>();
    fill_kernel<<<EDGES / 256, 256>>>(eidx);
    prep_wt_kernel<<<(256  * 256  + 255) / 256, 256>>>(m1w, WT + WOFF_M1, 256,  256);
    prep_wt_kernel<<<(256  * 256  + 255) / 256, 256>>>(m2w, WT + WOFF_M2, 256,  256);
    prep_wt_kernel<<<(256  * 1024 + 255) / 256, 256>>>(d0w, WT + WOFF_D0, 256,  1024);
    prep_wt_kernel<<<(1024 * 1024 + 255) / 256, 256>>>(d1w, WT + WOFF_D1, 1024, 1024);
    prep_wt_kernel<<<(1024 * 256  + 255) / 256, 256>>>(d2w, WT + WOFF_D2, 1024, 256);

    // --- fused edge MLP layers 2+3 (in-place on Xa) ---
    gemm_fused23<<<EDGES / BM, 512, SMEM_BIG>>>(
        Xa, WT + WOFF_M1, m1b, WT + WOFF_M2, m2b, Xa);

    // --- scatter-sum via CSR gather, fused with LN1 ---
    gather_ln1_kernel<<<NNODES, 256>>>(Xa, h_V, ln1g, ln1b, hb, hh);

    // --- dense MLP ---
    gemm256<256, false><<<dim3(DD / BN2, NNODES / BM), 256, SMEM_256>>>(
        hh, WT + WOFF_D0, d0b, Xb, DD);
    gemm256<1024, false><<<dim3(DD / BN2, NNODES / BM), 256, SMEM_256>>>(
        Xb, WT + WOFF_D1, d1b, Xa, DD);
    gemm_ln2<<<NNODES / BM, 512, SMEM_BIG>>>(
        Xa, WT + WOFF_D2, d2b, hb, ln2g, ln2b, outf);
}

// round 12
// speedup vs baseline: 1.0686x; 1.0686x over previous
#include <cuda_runtime.h>
#include <cuda_fp16.h>
#include <stdint.h>

// ---------------- problem constants ----------------
#define EDGES   524288
#define NNODES  16384
#define HD      256
#define EIN     512
#define DD      1024

// ---------------- device scratch (no allocations allowed) ----------------
static __device__ int    g_idx64;
static __device__ __half g_WT[1835008];                   // all weights, [N][K] fp16
static __device__ __half g_Xa[(size_t)EDGES * HD];
static __device__ __half g_Xb[(size_t)EDGES * HD];
static __device__ float  g_h [(size_t)NNODES * HD];       // post-LN1 h (fp32 residual)
static __device__ __half g_hh[(size_t)NNODES * HD];       // post-LN1 h (fp16)
// CSR structures
static __device__ int    g_cnt[NNODES];
static __device__ int    g_off[NNODES + 1];
static __device__ int    g_cur[NNODES];
static __device__ int    g_elist[EDGES];

#define WOFF_M0 0         // [256][512]
#define WOFF_M1 131072    // [256][256]
#define WOFF_M2 196608    // [256][256]
#define WOFF_D0 262144    // [1024][256]
#define WOFF_D1 524288    // [1024][1024]
#define WOFF_D2 1572864   // [256][1024]

// ---------------- helpers ----------------
__device__ __forceinline__ float gelu_f(float x) {
    return 0.5f * x * (1.0f + erff(x * 0.70710678118654752f));
}
__device__ __forceinline__ void cpasync16(uint32_t dst, const void* src) {
    asm volatile("cp.async.cg.shared.global [%0], [%1], 16;" :: "r"(dst), "l"(src) : "memory");
}
__device__ __forceinline__ void cp_commit() {
    asm volatile("cp.async.commit_group;" ::: "memory");
}
__device__ __forceinline__ void ldsm4(uint32_t* r, uint32_t addr) {
    asm volatile("ldmatrix.sync.aligned.m8n8.x4.shared.b16 {%0,%1,%2,%3}, [%4];"
                 : "=r"(r[0]), "=r"(r[1]), "=r"(r[2]), "=r"(r[3]) : "r"(addr));
}
__device__ __forceinline__ void mma16816(float* c, const uint32_t* a, const uint32_t* b) {
    asm volatile("mma.sync.aligned.m16n8k16.row.col.f32.f16.f16.f32 "
                 "{%0,%1,%2,%3}, {%4,%5,%6,%7}, {%8,%9}, {%0,%1,%2,%3};"
                 : "+f"(c[0]), "+f"(c[1]), "+f"(c[2]), "+f"(c[3])
                 : "r"(a[0]), "r"(a[1]), "r"(a[2]), "r"(a[3]), "r"(b[0]), "r"(b[1]));
}

// ---------------- GEMM tiling constants ----------------
#define BM 128
#define BN 256
#define BK 64
#define ASTR 72                          // BK + 8 halfs: ldmatrix conflict-free
#define A_BYTES (BM * ASTR * 2)          // 18432 per stage
#define B_BYTES (BN * ASTR * 2)          // 36864 per stage
#define NSTAGE 3
#define SMEM_MMA (NSTAGE * (A_BYTES + B_BYTES))  // 165888
#define A2_OFF  0
#define B2_OFF  (4 * A_BYTES)

#define EPI_GELU 0
#define EPI_LN2  2

// ---------------- pipelined chunk consumer ----------------
// Fragment double-buffered: ldsm for (ks,jj+1) issues before the 8 HMMA of (ks,jj).
// aBase/bBase are per-warp, per-slot smem byte addresses (ks=0, jj=0, mi=0 position).
__device__ __forceinline__ void mma_chunk(float (&acc)[2][8][4], uint32_t aBase, uint32_t bBase) {
    uint32_t ab[2][2][4];   // [parity][mi][4]
    uint32_t bb[2][4];      // [parity][4]
    ldsm4(ab[0][0], aBase);
    ldsm4(ab[0][1], aBase + (uint32_t)(16 * ASTR * 2));
    ldsm4(bb[0],    bBase);
#pragma unroll
    for (int ks = 0; ks < 4; ks++) {
        const int ap = ks & 1;
#pragma unroll
        for (int jj = 0; jj < 4; jj++) {
            const int bp = jj & 1;
            if (jj < 3) {
                ldsm4(bb[bp ^ 1], bBase + (uint32_t)((((jj + 1) * 16) * ASTR + ks * 16) * 2));
            } else if (ks < 3) {
                ldsm4(bb[bp ^ 1],    bBase + (uint32_t)(((ks + 1) * 16) * 2));
                ldsm4(ab[ap ^ 1][0], aBase + (uint32_t)(((ks + 1) * 16) * 2));
                ldsm4(ab[ap ^ 1][1], aBase + (uint32_t)((16 * ASTR + (ks + 1) * 16) * 2));
            }
#pragma unroll
            for (int mi = 0; mi < 2; mi++) {
                mma16816(acc[mi][2 * jj],     ab[ap][mi], bb[bp]);
                mma16816(acc[mi][2 * jj + 1], ab[ap][mi], bb[bp] + 2);
            }
        }
    }
}

// ---------------- prep kernels ----------------
__global__ void detect_idx_kernel(const int* p) {
    if (threadIdx.x == 0 && blockIdx.x == 0) {
        int is64 = 1;
        for (int i = 1; i < 512; i += 2)
            if (p[i] != 0) { is64 = 0; break; }
        g_idx64 = is64;
    }
}

// W [K,N] fp32 row-major -> WT [N,K] fp16 row-major
__global__ void prep_wt_kernel(const float* __restrict__ W, __half* __restrict__ WT, int K, int N) {
    long long idx = (long long)blockIdx.x * blockDim.x + threadIdx.x;
    if (idx >= (long long)K * N) return;
    int k = (int)(idx / N);
    int n = (int)(idx % N);
    WT[(long long)n * K + k] = __float2half(W[idx]);
}

// ---------------- CSR build ----------------
__global__ void zero_cnt_kernel() {
    int i = blockIdx.x * 256 + threadIdx.x;
    if (i < NNODES) g_cnt[i] = 0;
}
__global__ void count_kernel(const void* __restrict__ eidx) {
    int e = blockIdx.x * 256 + threadIdx.x;
    int n = g_idx64 ? (int)((const long long*)eidx)[e] : ((const int*)eidx)[e];
    atomicAdd(&g_cnt[n], 1);
}
__global__ void scan_kernel() {
    __shared__ int part[1024];
    int t = threadIdx.x;
    int loc[16]; int s = 0;
#pragma unroll
    for (int i = 0; i < 16; i++) { loc[i] = g_cnt[t * 16 + i]; s += loc[i]; }
    part[t] = s;
    __syncthreads();
    for (int o = 1; o < 1024; o <<= 1) {
        int v = (t >= o) ? part[t - o] : 0;
        __syncthreads();
        part[t] += v;
        __syncthreads();
    }
    int run = (t == 0) ? 0 : part[t - 1];
#pragma unroll
    for (int i = 0; i < 16; i++) { g_off[t * 16 + i] = run; g_cur[t * 16 + i] = run; run += loc[i]; }
    if (t == 1023) g_off[NNODES] = run;
}
__global__ void fill_kernel(const void* __restrict__ eidx) {
    int e = blockIdx.x * 256 + threadIdx.x;
    int n = g_idx64 ? (int)((const long long*)eidx)[e] : ((const int*)eidx)[e];
    int pos = atomicAdd(&g_cur[n], 1);
    g_elist[pos] = e;
}

// ---------------- fused gather + LN1 ----------------
__global__ void gather_ln1_kernel(const __half* __restrict__ m,
                                  const float* __restrict__ hV,
                                  const float* __restrict__ g1, const float* __restrict__ b1,
                                  float* __restrict__ h, __half* __restrict__ hh) {
    __shared__ float sm1[8], sm2[8];
    const int n = blockIdx.x, c = threadIdx.x;
    const int wid = c >> 5, lane = c & 31;
    const int s = g_off[n], e = g_off[n + 1];
    float acc = 0.f;
    int i = s;
    for (; i + 4 <= e; i += 4) {
        int e0 = g_elist[i], e1 = g_elist[i + 1], e2 = g_elist[i + 2], e3 = g_elist[i + 3];
        acc += __half2float(m[(size_t)e0 * HD + c]);
        acc += __half2float(m[(size_t)e1 * HD + c]);
        acc += __half2float(m[(size_t)e2 * HD + c]);
        acc += __half2float(m[(size_t)e3 * HD + c]);
    }
    for (; i < e; i++)
        acc += __half2float(m[(size_t)g_elist[i] * HD + c]);

    const float v = hV[(size_t)n * HD + c] + acc * (1.0f / 30.0f);
    float s1 = v, s2 = v * v;
#pragma unroll
    for (int off = 16; off; off >>= 1) {
        s1 += __shfl_xor_sync(0xffffffffu, s1, off);
        s2 += __shfl_xor_sync(0xffffffffu, s2, off);
    }
    if (lane == 0) { sm1[wid] = s1; sm2[wid] = s2; }
    __syncthreads();
    float t1 = 0.f, t2 = 0.f;
#pragma unroll
    for (int k = 0; k < 8; k++) { t1 += sm1[k]; t2 += sm2[k]; }
    const float mu  = t1 * (1.0f / HD);
    const float var = t2 * (1.0f / HD) - mu * mu;
    const float rs  = rsqrtf(var + 1e-5f);
    const float y = (v - mu) * rs * g1[c] + b1[c];
    h [(size_t)n * HD + c] = y;
    hh[(size_t)n * HD + c] = __float2half(y);
}

// ---------------- main GEMM (mma.sync, 512 thr, BK=64, 3-stage) ----------------
// AF32: A operand is fp32 in gmem; LDG->regs prefetched one iter ahead, STS as fp16.
template <int K, int EPI, bool AF32>
__global__ void __launch_bounds__(512, 1)
gemm_kernel(const void* __restrict__ Ain, const __half* __restrict__ WT_full,
            const float* __restrict__ bias_full,
            __half* __restrict__ out, int ldout,
            const float* __restrict__ h_res, const float* __restrict__ ln_g,
            const float* __restrict__ ln_b, float* __restrict__ outf) {
    extern __shared__ char smem[];
    __half* As = (__half*)smem;
    const int tid = threadIdx.x;
    const int m0  = blockIdx.x * BM;
    const int n0g = blockIdx.y * BN;
    const __half* WT  = WT_full + (size_t)n0g * K;
    const float* bias = bias_full + n0g;
    const __half* Ah  = (const __half*)Ain;
    const float*  Af  = (const float*)Ain;

    const uint32_t sA = (uint32_t)__cvta_generic_to_shared(smem);
    const uint32_t sB = sA + NSTAGE * A_BYTES;

    const int lane = tid & 31, warp = tid >> 5;
    const int wm = warp & 3, wn = warp >> 2;      // 4 m-warps x 4 n-warps; warp tile 32x64
    const int ml = lane & 7, tl = lane >> 3;

    // per-warp ldsm base offsets (bytes)
    const uint32_t aW = (uint32_t)(((wm * 32 + ml + (tl & 1) * 8) * ASTR + (tl >> 1) * 8) * 2);
    const uint32_t bW = (uint32_t)(((wn * 64 + ml + (tl >> 1) * 8) * ASTR + (tl & 1) * 8) * 2);

    float4 ra[2][2];
    auto ldgA = [&](int kc) {
        if constexpr (AF32) {
#pragma unroll
            for (int i = 0; i < 2; i++) {
                int idx = tid + i * 512;
                int r = idx >> 3, q = idx & 7;
                const float4* p = (const float4*)(Af + (size_t)(m0 + r) * K + kc * BK + q * 8);
                ra[i][0] = p[0];
                ra[i][1] = p[1];
            }
        }
    };
    auto stsA = [&](int slot) {
        if constexpr (AF32) {
#pragma unroll
            for (int i = 0; i < 2; i++) {
                int idx = tid + i * 512;
                int r = idx >> 3, q = idx & 7;
                alignas(16) __half2 hv[4];
                hv[0] = __floats2half2_rn(ra[i][0].x, ra[i][0].y);
                hv[1] = __floats2half2_rn(ra[i][0].z, ra[i][0].w);
                hv[2] = __floats2half2_rn(ra[i][1].x, ra[i][1].y);
                hv[3] = __floats2half2_rn(ra[i][1].z, ra[i][1].w);
                *(uint4*)(As + slot * (A_BYTES / 2) + r * ASTR + q * 8) = *(uint4*)hv;
            }
        }
    };
    auto issueB = [&](int kc, int slot) {
        if constexpr (!AF32) {
#pragma unroll
            for (int i = 0; i < 2; i++) {
                int idx = tid + i * 512;
                int r = idx >> 3, q = idx & 7;
                cpasync16(sA + slot * A_BYTES + (uint32_t)((r * ASTR + q * 8) * 2),
                          Ah + (size_t)(m0 + r) * K + kc * BK + q * 8);
            }
        }
#pragma unroll
        for (int i = 0; i < 4; i++) {
            int idx = tid + i * 512;
            int r = idx >> 3, q = idx & 7;
            cpasync16(sB + slot * B_BYTES + (uint32_t)((r * ASTR + q * 8) * 2),
                      WT + (size_t)r * K + kc * BK + q * 8);
        }
        cp_commit();
    };

    float acc[2][8][4];
#pragma unroll
    for (int mi = 0; mi < 2; mi++)
#pragma unroll
        for (int nj = 0; nj < 8; nj++)
#pragma unroll
            for (int j = 0; j < 4; j++) acc[mi][nj][j] = 0.f;

    const int NC = K / BK;
    ldgA(0); stsA(0); issueB(0, 0);
    ldgA(1); stsA(1); issueB(1, 1);
    ldgA(2);

    for (int c = 0; c < NC; c++) {
        const int slot = c % NSTAGE;
        if (c + 1 < NC) asm volatile("cp.async.wait_group 1;" ::: "memory");
        else            asm volatile("cp.async.wait_group 0;" ::: "memory");
        __syncthreads();
        if (c + 2 < NC) {
            stsA((c + 2) % NSTAGE);
            issueB(c + 2, (c + 2) % NSTAGE);
            if (c + 3 < NC) ldgA(c + 3);
        }
        mma_chunk(acc, sA + slot * A_BYTES + aW, sB + slot * B_BYTES + bW);
    }

    const int g  = lane >> 2;
    const int t2 = (lane & 3) * 2;

    if constexpr (EPI == EPI_GELU) {
#pragma unroll
        for (int mi = 0; mi < 2; mi++) {
            const int r0 = wm * 32 + mi * 16 + g;
#pragma unroll
            for (int nj = 0; nj < 8; nj++) {
                const int col = wn * 64 + nj * 8 + t2;
                const float b0v = bias[col], b1v = bias[col + 1];
                float x0 = gelu_f(acc[mi][nj][0] + b0v);
                float x1 = gelu_f(acc[mi][nj][1] + b1v);
                *(__half2*)(out + (size_t)(m0 + r0) * ldout + n0g + col) = __floats2half2_rn(x0, x1);
                float x2 = gelu_f(acc[mi][nj][2] + b0v);
                float x3 = gelu_f(acc[mi][nj][3] + b1v);
                *(__half2*)(out + (size_t)(m0 + r0 + 8) * ldout + n0g + col) = __floats2half2_rn(x2, x3);
            }
        }
    } else {  // EPI_LN2
        __syncthreads();
        float* sb = (float*)smem;
#pragma unroll
        for (int mi = 0; mi < 2; mi++) {
            const int r0 = wm * 32 + mi * 16 + g;
#pragma unroll
            for (int nj = 0; nj < 8; nj++) {
                const int col = wn * 64 + nj * 8 + t2;
                const float b0v = bias[col], b1v = bias[col + 1];
                sb[r0 * 264 + col]           = acc[mi][nj][0] + b0v + h_res[(size_t)(m0 + r0) * HD + col];
                sb[r0 * 264 + col + 1]       = acc[mi][nj][1] + b1v + h_res[(size_t)(m0 + r0) * HD + col + 1];
                sb[(r0 + 8) * 264 + col]     = acc[mi][nj][2] + b0v + h_res[(size_t)(m0 + r0 + 8) * HD + col];
                sb[(r0 + 8) * 264 + col + 1] = acc[mi][nj][3] + b1v + h_res[(size_t)(m0 + r0 + 8) * HD + col + 1];
            }
        }
        __syncthreads();
        for (int rr = 0; rr < 8; rr++) {
            const int row = warp * 8 + rr;
            float s = 0.f, s2 = 0.f;
#pragma unroll
            for (int i = 0; i < 8; i++) {
                float v = sb[row * 264 + lane + i * 32];
                s += v; s2 += v * v;
            }
#pragma unroll
            for (int off = 16; off; off >>= 1) {
                s  += __shfl_xor_sync(0xffffffffu, s, off);
                s2 += __shfl_xor_sync(0xffffffffu, s2, off);
            }
            const float mu  = s * (1.0f / HD);
            const float var = s2 * (1.0f / HD) - mu * mu;
            const float rs  = rsqrtf(var + 1e-5f);
#pragma unroll
            for (int i = 0; i < 8; i++) {
                const int cc = lane + i * 32;
                const float v = sb[row * 264 + cc];
                outf[(size_t)(m0 + row) * HD + cc] = (v - mu) * rs * ln_g[cc] + ln_b[cc];
            }
        }
    }
}

// ---------------- fused edge GEMM2+GEMM3 (512 thr, BN=256) ----------------
__global__ void __launch_bounds__(512, 1)
gemm_fused23(const __half* __restrict__ Xin,
             const __half* __restrict__ W1, const float* __restrict__ b1,
             const __half* __restrict__ W2, const float* __restrict__ b2,
             __half* __restrict__ out) {
    extern __shared__ char smem[];
    __half* As2 = (__half*)smem;
    const int tid = threadIdx.x;
    const int m0  = blockIdx.x * BM;

    const uint32_t sA  = (uint32_t)__cvta_generic_to_shared(smem);
    const uint32_t sB  = sA + NSTAGE * A_BYTES;
    const uint32_t sA2 = sA + A2_OFF;
    const uint32_t sB2 = sA + B2_OFF;

    const int lane = tid & 31, warp = tid >> 5;
    const int wm = warp & 3, wn = warp >> 2;
    const int ml = lane & 7, tl = lane >> 3;

    const uint32_t aW = (uint32_t)(((wm * 32 + ml + (tl & 1) * 8) * ASTR + (tl >> 1) * 8) * 2);
    const uint32_t bW = (uint32_t)(((wn * 64 + ml + (tl >> 1) * 8) * ASTR + (tl & 1) * 8) * 2);

    auto issue1 = [&](int kc, int slot) {
#pragma unroll
        for (int i = 0; i < 2; i++) {
            int idx = tid + i * 512;
            int r = idx >> 3, q = idx & 7;
            cpasync16(sA + slot * A_BYTES + (uint32_t)((r * ASTR + q * 8) * 2),
                      Xin + (size_t)(m0 + r) * 256 + kc * BK + q * 8);
        }
#pragma unroll
        for (int i = 0; i < 4; i++) {
            int idx = tid + i * 512;
            int r = idx >> 3, q = idx & 7;
            cpasync16(sB + slot * B_BYTES + (uint32_t)((r * ASTR + q * 8) * 2),
                      W1 + (size_t)r * 256 + kc * BK + q * 8);
        }
        cp_commit();
    };
    auto issue2 = [&](int kc, int slot) {
#pragma unroll
        for (int i = 0; i < 4; i++) {
            int idx = tid + i * 512;
            int r = idx >> 3, q = idx & 7;
            cpasync16(sB2 + slot * B_BYTES + (uint32_t)((r * ASTR + q * 8) * 2),
                      W2 + (size_t)r * 256 + kc * BK + q * 8);
        }
        cp_commit();
    };

    float acc[2][8][4];
#pragma unroll
    for (int mi = 0; mi < 2; mi++)
#pragma unroll
        for (int nj = 0; nj < 8; nj++)
#pragma unroll
            for (int j = 0; j < 4; j++) acc[mi][nj][j] = 0.f;

    issue1(0, 0);
    issue1(1, 1);
    for (int c = 0; c < 4; c++) {
        const int slot = c % NSTAGE;
        if (c + 1 < 4) asm volatile("cp.async.wait_group 1;" ::: "memory");
        else           asm volatile("cp.async.wait_group 0;" ::: "memory");
        __syncthreads();
        if (c + 2 < 4) issue1(c + 2, (c + 2) % NSTAGE);
        mma_chunk(acc, sA + slot * A_BYTES + aW, sB + slot * B_BYTES + bW);
    }

    __syncthreads();
    {
        const int g  = lane >> 2;
        const int t2 = (lane & 3) * 2;
#pragma unroll
        for (int mi = 0; mi < 2; mi++) {
            const int r0 = wm * 32 + mi * 16 + g;
#pragma unroll
            for (int nj = 0; nj < 8; nj++) {
                const int cl  = nj * 8 + t2;
                const int col = wn * 64 + cl;
                const float b0v = b1[col], b1v = b1[col + 1];
                __half2 v01 = __floats2half2_rn(gelu_f(acc[mi][nj][0] + b0v),
                                                gelu_f(acc[mi][nj][1] + b1v));
                __half2 v23 = __floats2half2_rn(gelu_f(acc[mi][nj][2] + b0v),
                                                gelu_f(acc[mi][nj][3] + b1v));
                *(__half2*)(As2 + wn * (A_BYTES / 2) + r0 * ASTR + cl)       = v01;
                *(__half2*)(As2 + wn * (A_BYTES / 2) + (r0 + 8) * ASTR + cl) = v23;
                acc[mi][nj][0] = acc[mi][nj][1] = acc[mi][nj][2] = acc[mi][nj][3] = 0.f;
            }
        }
    }
    __syncthreads();
    issue2(0, 0);
    issue2(1, 1);

    for (int c = 0; c < 4; c++) {
        const int slot = c & 1;
        if (c + 1 < 4) asm volatile("cp.async.wait_group 1;" ::: "memory");
        else           asm volatile("cp.async.wait_group 0;" ::: "memory");
        __syncthreads();
        mma_chunk(acc, sA2 + c * A_BYTES + aW, sB2 + slot * B_BYTES + bW);
        __syncthreads();
        if (c + 2 < 4) issue2(c + 2, slot);
    }

    {
        const int g  = lane >> 2;
        const int t2 = (lane & 3) * 2;
#pragma unroll
        for (int mi = 0; mi < 2; mi++) {
            const int r0 = wm * 32 + mi * 16 + g;
#pragma unroll
            for (int nj = 0; nj < 8; nj++) {
                const int col = wn * 64 + nj * 8 + t2;
                const float b0v = b2[col], b1v = b2[col + 1];
                float x0 = gelu_f(acc[mi][nj][0] + b0v);
                float x1 = gelu_f(acc[mi][nj][1] + b1v);
                *(__half2*)(out + (size_t)(m0 + r0) * HD + col) = __floats2half2_rn(x0, x1);
                float x2 = gelu_f(acc[mi][nj][2] + b0v);
                float x3 = gelu_f(acc[mi][nj][3] + b1v);
                *(__half2*)(out + (size_t)(m0 + r0 + 8) * HD + col) = __floats2half2_rn(x2, x3);
            }
        }
    }
}

// ---------------- host launcher ----------------
extern "C" void kernel_launch(void* const* d_in, const int* in_sizes, int n_in,
                              void* d_out, int out_size) {
    const float* h_V  = (const float*)d_in[0];
    const float* h_E  = (const float*)d_in[1];
    const void*  eidx = d_in[2];
    const float* m0w  = (const float*)d_in[3];
    const float* m0b  = (const float*)d_in[4];
    const float* m1w  = (const float*)d_in[5];
    const float* m1b  = (const float*)d_in[6];
    const float* m2w  = (const float*)d_in[7];
    const float* m2b  = (const float*)d_in[8];
    const float* d0w  = (const float*)d_in[9];
    const float* d0b  = (const float*)d_in[10];
    const float* d1w  = (const float*)d_in[11];
    const float* d1b  = (const float*)d_in[12];
    const float* d2w  = (const float*)d_in[13];
    const float* d2b  = (const float*)d_in[14];
    const float* ln1g = (const float*)d_in[15];
    const float* ln1b = (const float*)d_in[16];
    const float* ln2g = (const float*)d_in[17];
    const float* ln2b = (const float*)d_in[18];
    float* outf = (float*)d_out;
    (void)n_in; (void)out_size; (void)in_sizes;

    void *pWT, *pXa, *pXb, *pH, *pHH;
    cudaGetSymbolAddress(&pWT, g_WT);
    cudaGetSymbolAddress(&pXa, g_Xa);
    cudaGetSymbolAddress(&pXb, g_Xb);
    cudaGetSymbolAddress(&pH,  g_h);
    cudaGetSymbolAddress(&pHH, g_hh);
    __half* WT = (__half*)pWT;
    __half* Xa = (__half*)pXa;
    __half* Xb = (__half*)pXb;
    float*  hb = (float*)pH;
    __half* hh = (__half*)pHH;

    cudaFuncSetAttribute(gemm_kernel<512,  EPI_GELU, true>,  cudaFuncAttributeMaxDynamicSharedMemorySize, SMEM_MMA);
    cudaFuncSetAttribute(gemm_kernel<256,  EPI_GELU, false>, cudaFuncAttributeMaxDynamicSharedMemorySize, SMEM_MMA);
    cudaFuncSetAttribute(gemm_kernel<1024, EPI_GELU, false>, cudaFuncAttributeMaxDynamicSharedMemorySize, SMEM_MMA);
    cudaFuncSetAttribute(gemm_kernel<1024, EPI_LN2,  false>, cudaFuncAttributeMaxDynamicSharedMemorySize, SMEM_MMA);
    cudaFuncSetAttribute(gemm_fused23, cudaFuncAttributeMaxDynamicSharedMemorySize, SMEM_MMA);

    // --- launch order: GEMM1 is the 4th launch (ncu capture slot) ---
    detect_idx_kernel<<<1, 32>>>((const int*)eidx);                                // 1
    prep_wt_kernel<<<(512 * 256 + 255) / 256, 256>>>(m0w, WT + WOFF_M0, 512, 256); // 2
    zero_cnt_kernel<<<NNODES / 256, 256>>>();                                      // 3
    gemm_kernel<512, EPI_GELU, true><<<dim3(EDGES / BM, 1), 512, SMEM_MMA>>>(      // 4 <- profiled
        h_E, WT + WOFF_M0, m0b, Xa, HD, nullptr, nullptr, nullptr, nullptr);

    count_kernel<<<EDGES / 256, 256>>>(eidx);
    scan_kernel<<<1, 1024>>>();
    fill_kernel<<<EDGES / 256, 256>>>(eidx);
    prep_wt_kernel<<<(256  * 256  + 255) / 256, 256>>>(m1w, WT + WOFF_M1, 256,  256);
    prep_wt_kernel<<<(256  * 256  + 255) / 256, 256>>>(m2w, WT + WOFF_M2, 256,  256);
    prep_wt_kernel<<<(256  * 1024 + 255) / 256, 256>>>(d0w, WT + WOFF_D0, 256,  1024);
    prep_wt_kernel<<<(1024 * 1024 + 255) / 256, 256>>>(d1w, WT + WOFF_D1, 1024, 1024);
    prep_wt_kernel<<<(1024 * 256  + 255) / 256, 256>>>(d2w, WT + WOFF_D2, 1024, 256);

    // --- fused edge MLP layers 2+3 (in-place on Xa) ---
    gemm_fused23<<<EDGES / BM, 512, SMEM_MMA>>>(
        Xa, WT + WOFF_M1, m1b, WT + WOFF_M2, m2b, Xa);

    // --- scatter-sum via CSR gather, fused with LN1 ---
    gather_ln1_kernel<<<NNODES, 256>>>(Xa, h_V, ln1g, ln1b, hb, hh);

    // --- dense MLP ---
    gemm_kernel<256, EPI_GELU, false><<<dim3(NNODES / BM, 4), 512, SMEM_MMA>>>(
        hh, WT + WOFF_D0, d0b, Xb, DD, nullptr, nullptr, nullptr, nullptr);
    gemm_kernel<1024, EPI_GELU, false><<<dim3(NNODES / BM, 4), 512, SMEM_MMA>>>(
        Xb, WT + WOFF_D1, d1b, Xa, DD, nullptr, nullptr, nullptr, nullptr);
    gemm_kernel<1024, EPI_LN2, false><<<dim3(NNODES / BM, 1), 512, SMEM_MMA>>>(
        Xa, WT + WOFF_D2, d2b, nullptr, 0, hb, ln2g, ln2b, outf);
}

// round 15
// speedup vs baseline: 1.0891x; 1.0192x over previous
#include <cuda_runtime.h>
#include <cuda_fp16.h>
#include <stdint.h>

// ---------------- problem constants ----------------
#define EDGES   524288
#define NNODES  16384
#define HD      256
#define EIN     512
#define DD      1024

// ---------------- device scratch (no allocations allowed) ----------------
static __device__ int    g_idx64;
static __device__ __half g_WT[1835008];                   // all weights, [N][K] fp16
static __device__ __half g_Xa[(size_t)EDGES * HD];
static __device__ __half g_Xb[(size_t)EDGES * HD];
static __device__ float  g_h [(size_t)NNODES * HD];       // post-LN1 h (fp32 residual)
static __device__ __half g_hh[(size_t)NNODES * HD];       // post-LN1 h (fp16)
// CSR structures
static __device__ int    g_cnt[NNODES];
static __device__ int    g_off[NNODES + 1];
static __device__ int    g_cur[NNODES];
static __device__ int    g_elist[EDGES];

#define WOFF_M0 0         // [256][512]
#define WOFF_M1 131072    // [256][256]
#define WOFF_M2 196608    // [256][256]
#define WOFF_D0 262144    // [1024][256]
#define WOFF_D1 524288    // [1024][1024]
#define WOFF_D2 1572864   // [256][1024]

// ---------------- helpers ----------------
__device__ __forceinline__ float gelu_f(float x) {
    return 0.5f * x * (1.0f + erff(x * 0.70710678118654752f));
}
__device__ __forceinline__ void cpasync16(uint32_t dst, const void* src) {
    asm volatile("cp.async.cg.shared.global [%0], [%1], 16;" :: "r"(dst), "l"(src) : "memory");
}
__device__ __forceinline__ void cp_commit() {
    asm volatile("cp.async.commit_group;" ::: "memory");
}
__device__ __forceinline__ void ldsm4(uint32_t* r, uint32_t addr) {
    asm volatile("ldmatrix.sync.aligned.m8n8.x4.shared.b16 {%0,%1,%2,%3}, [%4];"
                 : "=r"(r[0]), "=r"(r[1]), "=r"(r[2]), "=r"(r[3]) : "r"(addr));
}
__device__ __forceinline__ void mma16816(float* c, const uint32_t* a, const uint32_t* b) {
    asm volatile("mma.sync.aligned.m16n8k16.row.col.f32.f16.f16.f32 "
                 "{%0,%1,%2,%3}, {%4,%5,%6,%7}, {%8,%9}, {%0,%1,%2,%3};"
                 : "+f"(c[0]), "+f"(c[1]), "+f"(c[2]), "+f"(c[3])
                 : "r"(a[0]), "r"(a[1]), "r"(a[2]), "r"(a[3]), "r"(b[0]), "r"(b[1]));
}

// ---------------- GEMM tiling constants ----------------
#define BM 128
#define BN 256
#define BK 64
#define ASTR 72                          // BK + 8 halfs: ldmatrix conflict-free
#define A_BYTES (BM * ASTR * 2)          // 18432 per stage
#define B_BYTES (BN * ASTR * 2)          // 36864 per stage
#define NSTAGE 3
#define SMEM_MMA (NSTAGE * (A_BYTES + B_BYTES))  // 165888
#define A2_OFF  0
#define B2_OFF  (4 * A_BYTES)            // 73728 .. 147456 (disjoint from A2)

// ln2 kernel (BM=64) constants
#define BM64 64
#define A64_BYTES (BM64 * ASTR * 2)      // 9216 per stage
#define SMEM_LN64 (NSTAGE * (A64_BYTES + B_BYTES))  // 138240

#define EPI_GELU 0

// ---------------- chunk consumer (plain; frag-buffering proved neutral) ----------------
__device__ __forceinline__ void mma_chunk(float (&acc)[2][8][4], uint32_t aBase, uint32_t bBase) {
#pragma unroll
    for (int ks = 0; ks < 4; ks++) {
        const uint32_t kb = (uint32_t)(ks * 16 * 2);
        uint32_t afr[2][4];
#pragma unroll
        for (int mi = 0; mi < 2; mi++)
            ldsm4(afr[mi], aBase + kb + (uint32_t)(mi * 16 * ASTR * 2));
#pragma unroll
        for (int jj = 0; jj < 4; jj++) {
            uint32_t bfr[4];
            ldsm4(bfr, bBase + kb + (uint32_t)(jj * 16 * ASTR * 2));
#pragma unroll
            for (int mi = 0; mi < 2; mi++) {
                mma16816(acc[mi][2 * jj],     afr[mi], bfr);
                mma16816(acc[mi][2 * jj + 1], afr[mi], bfr + 2);
            }
        }
    }
}

// ---------------- prep kernels ----------------
__global__ void detect_idx_kernel(const int* p) {
    if (threadIdx.x == 0 && blockIdx.x == 0) {
        int is64 = 1;
        for (int i = 1; i < 512; i += 2)
            if (p[i] != 0) { is64 = 0; break; }
        g_idx64 = is64;
    }
}

// all six W [K,N] fp32 -> WT [N,K] fp16, one launch
__global__ void prep_all_kernel(const float* __restrict__ m0w, const float* __restrict__ m1w,
                                const float* __restrict__ m2w, const float* __restrict__ d0w,
                                const float* __restrict__ d1w, const float* __restrict__ d2w,
                                __half* __restrict__ WT) {
    int idx = blockIdx.x * 256 + threadIdx.x;
    const float* W; int K, N, loc, woff;
    if (idx < 131072)       { W = m0w; K = 512;  N = 256;  loc = idx;           woff = WOFF_M0; }
    else if (idx < 196608)  { W = m1w; K = 256;  N = 256;  loc = idx - 131072;  woff = WOFF_M1; }
    else if (idx < 262144)  { W = m2w; K = 256;  N = 256;  loc = idx - 196608;  woff = WOFF_M2; }
    else if (idx < 524288)  { W = d0w; K = 256;  N = 1024; loc = idx - 262144;  woff = WOFF_D0; }
    else if (idx < 1572864) { W = d1w; K = 1024; N = 1024; loc = idx - 524288;  woff = WOFF_D1; }
    else                    { W = d2w; K = 1024; N = 256;  loc = idx - 1572864; woff = WOFF_D2; }
    int k = loc / N;
    int n = loc % N;
    WT[(long long)woff + (long long)n * K + k] = __float2half(W[loc]);
}

// ---------------- CSR build ----------------
__global__ void zero_cnt_kernel() {
    int i = blockIdx.x * 256 + threadIdx.x;
    if (i < NNODES) g_cnt[i] = 0;
}
__global__ void count_kernel(const void* __restrict__ eidx) {
    int e = blockIdx.x * 256 + threadIdx.x;
    int n = g_idx64 ? (int)((const long long*)eidx)[e] : ((const int*)eidx)[e];
    atomicAdd(&g_cnt[n], 1);
}
__global__ void scan_kernel() {
    __shared__ int part[1024];
    int t = threadIdx.x;
    int loc[16]; int s = 0;
#pragma unroll
    for (int i = 0; i < 16; i++) { loc[i] = g_cnt[t * 16 + i]; s += loc[i]; }
    part[t] = s;
    __syncthreads();
    for (int o = 1; o < 1024; o <<= 1) {
        int v = (t >= o) ? part[t - o] : 0;
        __syncthreads();
        part[t] += v;
        __syncthreads();
    }
    int run = (t == 0) ? 0 : part[t - 1];
#pragma unroll
    for (int i = 0; i < 16; i++) { g_off[t * 16 + i] = run; g_cur[t * 16 + i] = run; run += loc[i]; }
    if (t == 1023) g_off[NNODES] = run;
}
__global__ void fill_kernel(const void* __restrict__ eidx) {
    int e = blockIdx.x * 256 + threadIdx.x;
    int n = g_idx64 ? (int)((const long long*)eidx)[e] : ((const int*)eidx)[e];
    int pos = atomicAdd(&g_cur[n], 1);
    g_elist[pos] = e;
}

// ---------------- fused gather + LN1 ----------------
__global__ void gather_ln1_kernel(const __half* __restrict__ m,
                                  const float* __restrict__ hV,
                                  const float* __restrict__ g1, const float* __restrict__ b1,
                                  float* __restrict__ h, __half* __restrict__ hh) {
    __shared__ float sm1[8], sm2[8];
    const int n = blockIdx.x, c = threadIdx.x;
    const int wid = c >> 5, lane = c & 31;
    const int s = g_off[n], e = g_off[n + 1];
    float acc = 0.f;
    int i = s;
    for (; i + 4 <= e; i += 4) {
        int e0 = g_elist[i], e1 = g_elist[i + 1], e2 = g_elist[i + 2], e3 = g_elist[i + 3];
        acc += __half2float(m[(size_t)e0 * HD + c]);
        acc += __half2float(m[(size_t)e1 * HD + c]);
        acc += __half2float(m[(size_t)e2 * HD + c]);
        acc += __half2float(m[(size_t)e3 * HD + c]);
    }
    for (; i < e; i++)
        acc += __half2float(m[(size_t)g_elist[i] * HD + c]);

    const float v = hV[(size_t)n * HD + c] + acc * (1.0f / 30.0f);
    float s1 = v, s2 = v * v;
#pragma unroll
    for (int off = 16; off; off >>= 1) {
        s1 += __shfl_xor_sync(0xffffffffu, s1, off);
        s2 += __shfl_xor_sync(0xffffffffu, s2, off);
    }
    if (lane == 0) { sm1[wid] = s1; sm2[wid] = s2; }
    __syncthreads();
    float t1 = 0.f, t2 = 0.f;
#pragma unroll
    for (int k = 0; k < 8; k++) { t1 += sm1[k]; t2 += sm2[k]; }
    const float mu  = t1 * (1.0f / HD);
    const float var = t2 * (1.0f / HD) - mu * mu;
    const float rs  = rsqrtf(var + 1e-5f);
    const float y = (v - mu) * rs * g1[c] + b1[c];
    h [(size_t)n * HD + c] = y;
    hh[(size_t)n * HD + c] = __float2half(y);
}

// ---------------- main GEMM (mma.sync, 512 thr, BK=64, 3-stage) ----------------
template <int K, int EPI, bool AF32>
__global__ void __launch_bounds__(512, 1)
gemm_kernel(const void* __restrict__ Ain, const __half* __restrict__ WT_full,
            const float* __restrict__ bias_full,
            __half* __restrict__ out, int ldout) {
    extern __shared__ char smem[];
    __half* As = (__half*)smem;
    const int tid = threadIdx.x;
    const int m0  = blockIdx.x * BM;
    const int n0g = blockIdx.y * BN;
    const __half* WT  = WT_full + (size_t)n0g * K;
    const float* bias = bias_full + n0g;
    const __half* Ah  = (const __half*)Ain;
    const float*  Af  = (const float*)Ain;

    const uint32_t sA = (uint32_t)__cvta_generic_to_shared(smem);
    const uint32_t sB = sA + NSTAGE * A_BYTES;

    const int lane = tid & 31, warp = tid >> 5;
    const int wm = warp & 3, wn = warp >> 2;      // 4 m-warps x 4 n-warps; warp tile 32x64
    const int ml = lane & 7, tl = lane >> 3;

    const uint32_t aW = (uint32_t)(((wm * 32 + ml + (tl & 1) * 8) * ASTR + (tl >> 1) * 8) * 2);
    const uint32_t bW = (uint32_t)(((wn * 64 + ml + (tl >> 1) * 8) * ASTR + (tl & 1) * 8) * 2);

    float4 ra[2][2];
    auto ldgA = [&](int kc) {
        if constexpr (AF32) {
#pragma unroll
            for (int i = 0; i < 2; i++) {
                int idx = tid + i * 512;
                int r = idx >> 3, q = idx & 7;
                const float4* p = (const float4*)(Af + (size_t)(m0 + r) * K + kc * BK + q * 8);
                ra[i][0] = p[0];
                ra[i][1] = p[1];
            }
        }
    };
    auto stsA = [&](int slot) {
        if constexpr (AF32) {
#pragma unroll
            for (int i = 0; i < 2; i++) {
                int idx = tid + i * 512;
                int r = idx >> 3, q = idx & 7;
                alignas(16) __half2 hv[4];
                hv[0] = __floats2half2_rn(ra[i][0].x, ra[i][0].y);
                hv[1] = __floats2half2_rn(ra[i][0].z, ra[i][0].w);
                hv[2] = __floats2half2_rn(ra[i][1].x, ra[i][1].y);
                hv[3] = __floats2half2_rn(ra[i][1].z, ra[i][1].w);
                *(uint4*)(As + slot * (A_BYTES / 2) + r * ASTR + q * 8) = *(uint4*)hv;
            }
        }
    };
    auto issueB = [&](int kc, int slot) {
        if constexpr (!AF32) {
#pragma unroll
            for (int i = 0; i < 2; i++) {
                int idx = tid + i * 512;
                int r = idx >> 3, q = idx & 7;
                cpasync16(sA + slot * A_BYTES + (uint32_t)((r * ASTR + q * 8) * 2),
                          Ah + (size_t)(m0 + r) * K + kc * BK + q * 8);
            }
        }
#pragma unroll
        for (int i = 0; i < 4; i++) {
            int idx = tid + i * 512;
            int r = idx >> 3, q = idx & 7;
            cpasync16(sB + slot * B_BYTES + (uint32_t)((r * ASTR + q * 8) * 2),
                      WT + (size_t)r * K + kc * BK + q * 8);
        }
        cp_commit();
    };

    float acc[2][8][4];
#pragma unroll
    for (int mi = 0; mi < 2; mi++)
#pragma unroll
        for (int nj = 0; nj < 8; nj++)
#pragma unroll
            for (int j = 0; j < 4; j++) acc[mi][nj][j] = 0.f;

    const int NC = K / BK;
    ldgA(0); stsA(0); issueB(0, 0);
    ldgA(1); stsA(1); issueB(1, 1);
    ldgA(2);

    for (int c = 0; c < NC; c++) {
        const int slot = c % NSTAGE;
        if (c + 1 < NC) asm volatile("cp.async.wait_group 1;" ::: "memory");
        else            asm volatile("cp.async.wait_group 0;" ::: "memory");
        __syncthreads();
        if (c + 2 < NC) {
            stsA((c + 2) % NSTAGE);
            issueB(c + 2, (c + 2) % NSTAGE);
            if (c + 3 < NC) ldgA(c + 3);
        }
        mma_chunk(acc, sA + slot * A_BYTES + aW, sB + slot * B_BYTES + bW);
    }

    // epilogue: gelu(acc + bias) -> fp16
    const int g  = lane >> 2;
    const int t2 = (lane & 3) * 2;
#pragma unroll
    for (int mi = 0; mi < 2; mi++) {
        const int r0 = wm * 32 + mi * 16 + g;
#pragma unroll
        for (int nj = 0; nj < 8; nj++) {
            const int col = wn * 64 + nj * 8 + t2;
            const float b0v = bias[col], b1v = bias[col + 1];
            float x0 = gelu_f(acc[mi][nj][0] + b0v);
            float x1 = gelu_f(acc[mi][nj][1] + b1v);
            *(__half2*)(out + (size_t)(m0 + r0) * ldout + n0g + col) = __floats2half2_rn(x0, x1);
            float x2 = gelu_f(acc[mi][nj][2] + b0v);
            float x3 = gelu_f(acc[mi][nj][3] + b1v);
            *(__half2*)(out + (size_t)(m0 + r0 + 8) * ldout + n0g + col) = __floats2half2_rn(x2, x3);
        }
    }
}

// ---------------- fused edge GEMM2+GEMM3 (512 thr, BN=256) ----------------
__global__ void __launch_bounds__(512, 1)
gemm_fused23(const __half* __restrict__ Xin,
             const __half* __restrict__ W1, const float* __restrict__ b1,
             const __half* __restrict__ W2, const float* __restrict__ b2,
             __half* __restrict__ out) {
    extern __shared__ char smem[];
    __half* As2 = (__half*)smem;
    const int tid = threadIdx.x;
    const int m0  = blockIdx.x * BM;

    const uint32_t sA  = (uint32_t)__cvta_generic_to_shared(smem);
    const uint32_t sB  = sA + NSTAGE * A_BYTES;
    const uint32_t sA2 = sA + A2_OFF;
    const uint32_t sB2 = sA + B2_OFF;

    const int lane = tid & 31, warp = tid >> 5;
    const int wm = warp & 3, wn = warp >> 2;
    const int ml = lane & 7, tl = lane >> 3;

    const uint32_t aW = (uint32_t)(((wm * 32 + ml + (tl & 1) * 8) * ASTR + (tl >> 1) * 8) * 2);
    const uint32_t bW = (uint32_t)(((wn * 64 + ml + (tl >> 1) * 8) * ASTR + (tl & 1) * 8) * 2);

    auto issue1 = [&](int kc, int slot) {
#pragma unroll
        for (int i = 0; i < 2; i++) {
            int idx = tid + i * 512;
            int r = idx >> 3, q = idx & 7;
            cpasync16(sA + slot * A_BYTES + (uint32_t)((r * ASTR + q * 8) * 2),
                      Xin + (size_t)(m0 + r) * 256 + kc * BK + q * 8);
        }
#pragma unroll
        for (int i = 0; i < 4; i++) {
            int idx = tid + i * 512;
            int r = idx >> 3, q = idx & 7;
            cpasync16(sB + slot * B_BYTES + (uint32_t)((r * ASTR + q * 8) * 2),
                      W1 + (size_t)r * 256 + kc * BK + q * 8);
        }
        cp_commit();
    };
    auto issue2 = [&](int kc, int slot) {
#pragma unroll
        for (int i = 0; i < 4; i++) {
            int idx = tid + i * 512;
            int r = idx >> 3, q = idx & 7;
            cpasync16(sB2 + slot * B_BYTES + (uint32_t)((r * ASTR + q * 8) * 2),
                      W2 + (size_t)r * 256 + kc * BK + q * 8);
        }
        cp_commit();
    };

    float acc[2][8][4];
#pragma unroll
    for (int mi = 0; mi < 2; mi++)
#pragma unroll
        for (int nj = 0; nj < 8; nj++)
#pragma unroll
            for (int j = 0; j < 4; j++) acc[mi][nj][j] = 0.f;

    issue1(0, 0);
    issue1(1, 1);
    for (int c = 0; c < 4; c++) {
        const int slot = c % NSTAGE;
        if (c + 1 < 4) asm volatile("cp.async.wait_group 1;" ::: "memory");
        else           asm volatile("cp.async.wait_group 0;" ::: "memory");
        __syncthreads();
        if (c + 2 < 4) issue1(c + 2, (c + 2) % NSTAGE);
        mma_chunk(acc, sA + slot * A_BYTES + aW, sB + slot * B_BYTES + bW);
    }

    __syncthreads();           // all stage-1 reads done
    issue2(0, 0);              // B2 prefetch hidden under X2 convert/store
    issue2(1, 1);
    {
        const int g  = lane >> 2;
        const int t2 = (lane & 3) * 2;
#pragma unroll
        for (int mi = 0; mi < 2; mi++) {
            const int r0 = wm * 32 + mi * 16 + g;
#pragma unroll
            for (int nj = 0; nj < 8; nj++) {
                const int cl  = nj * 8 + t2;
                const int col = wn * 64 + cl;
                const float b0v = b1[col], b1v = b1[col + 1];
                __half2 v01 = __floats2half2_rn(gelu_f(acc[mi][nj][0] + b0v),
                                                gelu_f(acc[mi][nj][1] + b1v));
                __half2 v23 = __floats2half2_rn(gelu_f(acc[mi][nj][2] + b0v),
                                                gelu_f(acc[mi][nj][3] + b1v));
                *(__half2*)(As2 + wn * (A_BYTES / 2) + r0 * ASTR + cl)       = v01;
                *(__half2*)(As2 + wn * (A_BYTES / 2) + (r0 + 8) * ASTR + cl) = v23;
                acc[mi][nj][0] = acc[mi][nj][1] = acc[mi][nj][2] = acc[mi][nj][3] = 0.f;
            }
        }
    }
    __syncthreads();           // A2 visible

    for (int c = 0; c < 4; c++) {
        const int slot = c & 1;
        if (c + 1 < 4) asm volatile("cp.async.wait_group 1;" ::: "memory");
        else           asm volatile("cp.async.wait_group 0;" ::: "memory");
        __syncthreads();
        mma_chunk(acc, sA2 + c * A_BYTES + aW, sB2 + slot * B_BYTES + bW);
        __syncthreads();
        if (c + 2 < 4) issue2(c + 2, slot);
    }

    {
        const int g  = lane >> 2;
        const int t2 = (lane & 3) * 2;
#pragma unroll
        for (int mi = 0; mi < 2; mi++) {
            const int r0 = wm * 32 + mi * 16 + g;
#pragma unroll
            for (int nj = 0; nj < 8; nj++) {
                const int col = wn * 64 + nj * 8 + t2;
                const float b0v = b2[col], b1v = b2[col + 1];
                float x0 = gelu_f(acc[mi][nj][0] + b0v);
                float x1 = gelu_f(acc[mi][nj][1] + b1v);
                *(__half2*)(out + (size_t)(m0 + r0) * HD + col) = __floats2half2_rn(x0, x1);
                float x2 = gelu_f(acc[mi][nj][2] + b0v);
                float x3 = gelu_f(acc[mi][nj][3] + b1v);
                *(__half2*)(out + (size_t)(m0 + r0 + 8) * HD + col) = __floats2half2_rn(x2, x3);
            }
        }
    }
}

// ---------------- final GEMM + LN2 (512 thr, BM=64, BN=256, K=1024) ----------------
__global__ void __launch_bounds__(512, 1)
gemm_ln2_64(const __half* __restrict__ Ah, const __half* __restrict__ WT,
            const float* __restrict__ bias,
            const float* __restrict__ h_res, const float* __restrict__ ln_g,
            const float* __restrict__ ln_b, float* __restrict__ outf) {
    constexpr int K = 1024;
    extern __shared__ char smem[];
    __half* As = (__half*)smem;
    const int tid = threadIdx.x;
    const int m0  = blockIdx.x * BM64;

    const uint32_t sA = (uint32_t)__cvta_generic_to_shared(smem);
    const uint32_t sB = sA + NSTAGE * A64_BYTES;

    const int lane = tid & 31, warp = tid >> 5;
    const int wm = warp & 3, wn = warp >> 2;      // 4 m-warps (16 rows) x 4 n-warps (64 cols)
    const int ml = lane & 7, tl = lane >> 3;

    const uint32_t aW = (uint32_t)(((wm * 16 + ml + (tl & 1) * 8) * ASTR + (tl >> 1) * 8) * 2);
    const uint32_t bW = (uint32_t)(((wn * 64 + ml + (tl >> 1) * 8) * ASTR + (tl & 1) * 8) * 2);

    auto issue = [&](int kc, int slot) {
        {   // A: 512 chunks, 1 per thread
            int r = tid >> 3, q = tid & 7;
            cpasync16(sA + slot * A64_BYTES + (uint32_t)((r * ASTR + q * 8) * 2),
                      Ah + (size_t)(m0 + r) * K + kc * BK + q * 8);
        }
#pragma unroll
        for (int i = 0; i < 4; i++) {   // B: 2048 chunks, 4 per thread
            int idx = tid + i * 512;
            int r = idx >> 3, q = idx & 7;
            cpasync16(sB + slot * B_BYTES + (uint32_t)((r * ASTR + q * 8) * 2),
                      WT + (size_t)r * K + kc * BK + q * 8);
        }
        cp_commit();
    };

    float acc[8][4];
#pragma unroll
    for (int nj = 0; nj < 8; nj++)
#pragma unroll
        for (int j = 0; j < 4; j++) acc[nj][j] = 0.f;

    const int NC = K / BK;   // 16
    issue(0, 0);
    issue(1, 1);
    for (int c = 0; c < NC; c++) {
        const int slot = c % NSTAGE;
        if (c + 1 < NC) asm volatile("cp.async.wait_group 1;" ::: "memory");
        else            asm volatile("cp.async.wait_group 0;" ::: "memory");
        __syncthreads();
        if (c + 2 < NC) issue(c + 2, (c + 2) % NSTAGE);

        const uint32_t aS = sA + slot * A64_BYTES + aW;
        const uint32_t bS = sB + slot * B_BYTES + bW;
#pragma unroll
        for (int ks = 0; ks < 4; ks++) {
            const uint32_t kb = (uint32_t)(ks * 16 * 2);
            uint32_t afr[4];
            ldsm4(afr, aS + kb);
#pragma unroll
            for (int jj = 0; jj < 4; jj++) {
                uint32_t bfr[4];
                ldsm4(bfr, bS + kb + (uint32_t)(jj * 16 * ASTR * 2));
                mma16816(acc[2 * jj],     afr, bfr);
                mma16816(acc[2 * jj + 1], afr, bfr + 2);
            }
        }
    }

    // LN2 epilogue over 64 rows
    __syncthreads();
    float* sb = (float*)smem;   // [64][264] = 67584 B
    const int g  = lane >> 2;
    const int t2 = (lane & 3) * 2;
    {
        const int r0 = wm * 16 + g;
#pragma unroll
        for (int nj = 0; nj < 8; nj++) {
            const int col = wn * 64 + nj * 8 + t2;
            const float b0v = bias[col], b1v = bias[col + 1];
            sb[r0 * 264 + col]           = acc[nj][0] + b0v + h_res[(size_t)(m0 + r0) * HD + col];
            sb[r0 * 264 + col + 1]       = acc[nj][1] + b1v + h_res[(size_t)(m0 + r0) * HD + col + 1];
            sb[(r0 + 8) * 264 + col]     = acc[nj][2] + b0v + h_res[(size_t)(m0 + r0 + 8) * HD + col];
            sb[(r0 + 8) * 264 + col + 1] = acc[nj][3] + b1v + h_res[(size_t)(m0 + r0 + 8) * HD + col + 1];
        }
    }
    __syncthreads();
    for (int rr = 0; rr < 4; rr++) {
        const int row = warp * 4 + rr;
        float s = 0.f, s2 = 0.f;
#pragma unroll
        for (int i = 0; i < 8; i++) {
            float v = sb[row * 264 + lane + i * 32];
            s += v; s2 += v * v;
        }
#pragma unroll
        for (int off = 16; off; off >>= 1) {
            s  += __shfl_xor_sync(0xffffffffu, s, off);
            s2 += __shfl_xor_sync(0xffffffffu, s2, off);
        }
        const float mu  = s * (1.0f / HD);
        const float var = s2 * (1.0f / HD) - mu * mu;
        const float rs  = rsqrtf(var + 1e-5f);
#pragma unroll
        for (int i = 0; i < 8; i++) {
            const int cc = lane + i * 32;
            const float v = sb[row * 264 + cc];
            outf[(size_t)(m0 + row) * HD + cc] = (v - mu) * rs * ln_g[cc] + ln_b[cc];
        }
    }
}

// ---------------- host launcher ----------------
extern "C" void kernel_launch(void* const* d_in, const int* in_sizes, int n_in,
                              void* d_out, int out_size) {
    const float* h_V  = (const float*)d_in[0];
    const float* h_E  = (const float*)d_in[1];
    const void*  eidx = d_in[2];
    const float* m0w  = (const float*)d_in[3];
    const float* m0b  = (const float*)d_in[4];
    const float* m1w  = (const float*)d_in[5];
    const float* m1b  = (const float*)d_in[6];
    const float* m2w  = (const float*)d_in[7];
    const float* m2b  = (const float*)d_in[8];
    const float* d0w  = (const float*)d_in[9];
    const float* d0b  = (const float*)d_in[10];
    const float* d1w  = (const float*)d_in[11];
    const float* d1b  = (const float*)d_in[12];
    const float* d2w  = (const float*)d_in[13];
    const float* d2b  = (const float*)d_in[14];
    const float* ln1g = (const float*)d_in[15];
    const float* ln1b = (const float*)d_in[16];
    const float* ln2g = (const float*)d_in[17];
    const float* ln2b = (const float*)d_in[18];
    float* outf = (float*)d_out;
    (void)n_in; (void)out_size; (void)in_sizes;

    void *pWT, *pXa, *pXb, *pH, *pHH;
    cudaGetSymbolAddress(&pWT, g_WT);
    cudaGetSymbolAddress(&pXa, g_Xa);
    cudaGetSymbolAddress(&pXb, g_Xb);
    cudaGetSymbolAddress(&pH,  g_h);
    cudaGetSymbolAddress(&pHH, g_hh);
    __half* WT = (__half*)pWT;
    __half* Xa = (__half*)pXa;
    __half* Xb = (__half*)pXb;
    float*  hb = (float*)pH;
    __half* hh = (__half*)pHH;

    cudaFuncSetAttribute(gemm_kernel<512,  EPI_GELU, true>,  cudaFuncAttributeMaxDynamicSharedMemorySize, SMEM_MMA);
    cudaFuncSetAttribute(gemm_kernel<256,  EPI_GELU, false>, cudaFuncAttributeMaxDynamicSharedMemorySize, SMEM_MMA);
    cudaFuncSetAttribute(gemm_kernel<1024, EPI_GELU, false>, cudaFuncAttributeMaxDynamicSharedMemorySize, SMEM_MMA);
    cudaFuncSetAttribute(gemm_fused23, cudaFuncAttributeMaxDynamicSharedMemorySize, SMEM_MMA);
    cudaFuncSetAttribute(gemm_ln2_64,  cudaFuncAttributeMaxDynamicSharedMemorySize, SMEM_LN64);

    // --- launch order: fused23 is the 4th launch (ncu capture slot) ---
    detect_idx_kernel<<<1, 32>>>((const int*)eidx);                                // 1
    prep_all_kernel<<<1835008 / 256, 256>>>(m0w, m1w, m2w, d0w, d1w, d2w, WT);     // 2
    gemm_kernel<512, EPI_GELU, true><<<dim3(EDGES / BM, 1), 512, SMEM_MMA>>>(      // 3
        h_E, WT + WOFF_M0, m0b, Xa, HD);
    gemm_fused23<<<EDGES / BM, 512, SMEM_MMA>>>(                                   // 4 <- profiled
        Xa, WT + WOFF_M1, m1b, WT + WOFF_M2, m2b, Xa);

    // --- CSR build ---
    zero_cnt_kernel<<<NNODES / 256, 256>>>();
    count_kernel<<<EDGES / 256, 256>>>(eidx);
    scan_kernel<<<1, 1024>>>();
    fill_kernel<<<EDGES / 256, 256>>>(eidx);

    // --- scatter-sum via CSR gather, fused with LN1 ---
    gather_ln1_kernel<<<NNODES, 256>>>(Xa, h_V, ln1g, ln1b, hb, hh);

    // --- dense MLP ---
    gemm_kernel<256, EPI_GELU, false><<<dim3(NNODES / BM, 4), 512, SMEM_MMA>>>(
        hh, WT + WOFF_D0, d0b, Xb, DD);
    gemm_kernel<1024, EPI_GELU, false><<<dim3(NNODES / BM, 4), 512, SMEM_MMA>>>(
        Xb, WT + WOFF_D1, d1b, Xa, DD);
    gemm_ln2_64<<<NNODES / BM64, 512, SMEM_LN64>>>(
        Xa, WT + WOFF_D2, d2b, hb, ln2g, ln2b, outf);
}

// round 16
// speedup vs baseline: 1.1462x; 1.0525x over previous
#include <cuda_runtime.h>
#include <cuda_fp16.h>
#include <stdint.h>

// ---------------- problem constants ----------------
#define EDGES   524288
#define NNODES  16384
#define HD      256
#define EIN     512
#define DD      1024

// ---------------- device scratch ----------------
static __device__ int    g_idx64;
static __device__ __half g_WT[1835008];
static __device__ __half g_Xa[(size_t)EDGES * HD];
static __device__ __half g_Xb[(size_t)EDGES * HD];
static __device__ float  g_h [(size_t)NNODES * HD];
static __device__ __half g_hh[(size_t)NNODES * HD];
static __device__ int    g_cnt[NNODES];
static __device__ int    g_off[NNODES + 1];
static __device__ int    g_cur[NNODES];
static __device__ int    g_elist[EDGES];

#define WOFF_M0 0
#define WOFF_M1 131072
#define WOFF_M2 196608
#define WOFF_D0 262144
#define WOFF_D1 524288
#define WOFF_D2 1572864

// ---------------- helpers ----------------
__device__ __forceinline__ float gelu_f(float x) {
    return 0.5f * x * (1.0f + erff(x * 0.70710678118654752f));
}
__device__ __forceinline__ void cpasync16(uint32_t dst, const void* src) {
    asm volatile("cp.async.cg.shared.global [%0], [%1], 16;" :: "r"(dst), "l"(src) : "memory");
}
__device__ __forceinline__ void cp_commit() {
    asm volatile("cp.async.commit_group;" ::: "memory");
}
__device__ __forceinline__ void ldsm4(uint32_t* r, uint32_t addr) {
    asm volatile("ldmatrix.sync.aligned.m8n8.x4.shared.b16 {%0,%1,%2,%3}, [%4];"
                 : "=r"(r[0]), "=r"(r[1]), "=r"(r[2]), "=r"(r[3]) : "r"(addr));
}
__device__ __forceinline__ void mma16816(float* c, const uint32_t* a, const uint32_t* b) {
    asm volatile("mma.sync.aligned.m16n8k16.row.col.f32.f16.f16.f32 "
                 "{%0,%1,%2,%3}, {%4,%5,%6,%7}, {%8,%9}, {%0,%1,%2,%3};"
                 : "+f"(c[0]), "+f"(c[1]), "+f"(c[2]), "+f"(c[3])
                 : "r"(a[0]), "r"(a[1]), "r"(a[2]), "r"(a[3]), "r"(b[0]), "r"(b[1]));
}

// ---------------- tiling constants ----------------
#define BM 128
#define BN 256
#define BK 64
#define ASTR 72
#define A_BYTES (BM * ASTR * 2)          // 18432
#define B_BYTES (BN * ASTR * 2)          // 36864
#define NSTAGE 3
#define SMEM_MMA (NSTAGE * (A_BYTES + B_BYTES))  // 165888
#define A2_OFF  0
#define B2_OFF  (4 * A_BYTES)

#define BM64 64
#define A64_BYTES (BM64 * ASTR * 2)      // 9216
#define SMEM64 (2 * (A64_BYTES + B_BYTES))  // 92160 -> 2 CTAs/SM

#define EPI_GELU 0
#define EPI_LN2  2

// ---------------- 128-row chunk consumer ----------------
__device__ __forceinline__ void mma_chunk(float (&acc)[2][8][4], uint32_t aBase, uint32_t bBase) {
#pragma unroll
    for (int ks = 0; ks < 4; ks++) {
        const uint32_t kb = (uint32_t)(ks * 16 * 2);
        uint32_t afr[2][4];
#pragma unroll
        for (int mi = 0; mi < 2; mi++)
            ldsm4(afr[mi], aBase + kb + (uint32_t)(mi * 16 * ASTR * 2));
#pragma unroll
        for (int jj = 0; jj < 4; jj++) {
            uint32_t bfr[4];
            ldsm4(bfr, bBase + kb + (uint32_t)(jj * 16 * ASTR * 2));
#pragma unroll
            for (int mi = 0; mi < 2; mi++) {
                mma16816(acc[mi][2 * jj],     afr[mi], bfr);
                mma16816(acc[mi][2 * jj + 1], afr[mi], bfr + 2);
            }
        }
    }
}

// ---------------- prep ----------------
__global__ void detect_idx_kernel(const int* p) {
    if (threadIdx.x == 0 && blockIdx.x == 0) {
        int is64 = 1;
        for (int i = 1; i < 512; i += 2)
            if (p[i] != 0) { is64 = 0; break; }
        g_idx64 = is64;
    }
}

__global__ void prep_all_kernel(const float* __restrict__ m0w, const float* __restrict__ m1w,
                                const float* __restrict__ m2w, const float* __restrict__ d0w,
                                const float* __restrict__ d1w, const float* __restrict__ d2w,
                                __half* __restrict__ WT) {
    int idx = blockIdx.x * 256 + threadIdx.x;
    const float* W; int K, N, loc, woff;
    if (idx < 131072)       { W = m0w; K = 512;  N = 256;  loc = idx;           woff = WOFF_M0; }
    else if (idx < 196608)  { W = m1w; K = 256;  N = 256;  loc = idx - 131072;  woff = WOFF_M1; }
    else if (idx < 262144)  { W = m2w; K = 256;  N = 256;  loc = idx - 196608;  woff = WOFF_M2; }
    else if (idx < 524288)  { W = d0w; K = 256;  N = 1024; loc = idx - 262144;  woff = WOFF_D0; }
    else if (idx < 1572864) { W = d1w; K = 1024; N = 1024; loc = idx - 524288;  woff = WOFF_D1; }
    else                    { W = d2w; K = 1024; N = 256;  loc = idx - 1572864; woff = WOFF_D2; }
    int k = loc / N;
    int n = loc % N;
    WT[(long long)woff + (long long)n * K + k] = __float2half(W[loc]);
}

// ---------------- CSR build ----------------
__global__ void zero_cnt_kernel() {
    int i = blockIdx.x * 256 + threadIdx.x;
    if (i < NNODES) g_cnt[i] = 0;
}
__global__ void count_kernel(const void* __restrict__ eidx) {
    int e = blockIdx.x * 256 + threadIdx.x;
    int n = g_idx64 ? (int)((const long long*)eidx)[e] : ((const int*)eidx)[e];
    atomicAdd(&g_cnt[n], 1);
}
__global__ void scan_kernel() {
    __shared__ int part[1024];
    int t = threadIdx.x;
    int loc[16]; int s = 0;
#pragma unroll
    for (int i = 0; i < 16; i++) { loc[i] = g_cnt[t * 16 + i]; s += loc[i]; }
    part[t] = s;
    __syncthreads();
    for (int o = 1; o < 1024; o <<= 1) {
        int v = (t >= o) ? part[t - o] : 0;
        __syncthreads();
        part[t] += v;
        __syncthreads();
    }
    int run = (t == 0) ? 0 : part[t - 1];
#pragma unroll
    for (int i = 0; i < 16; i++) { g_off[t * 16 + i] = run; g_cur[t * 16 + i] = run; run += loc[i]; }
    if (t == 1023) g_off[NNODES] = run;
}
__global__ void fill_kernel(const void* __restrict__ eidx) {
    int e = blockIdx.x * 256 + threadIdx.x;
    int n = g_idx64 ? (int)((const long long*)eidx)[e] : ((const int*)eidx)[e];
    int pos = atomicAdd(&g_cur[n], 1);
    g_elist[pos] = e;
}

// ---------------- fused gather + LN1 ----------------
__global__ void gather_ln1_kernel(const __half* __restrict__ m,
                                  const float* __restrict__ hV,
                                  const float* __restrict__ g1, const float* __restrict__ b1,
                                  float* __restrict__ h, __half* __restrict__ hh) {
    __shared__ float sm1[8], sm2[8];
    const int n = blockIdx.x, c = threadIdx.x;
    const int wid = c >> 5, lane = c & 31;
    const int s = g_off[n], e = g_off[n + 1];
    float acc = 0.f;
    int i = s;
    for (; i + 4 <= e; i += 4) {
        int e0 = g_elist[i], e1 = g_elist[i + 1], e2 = g_elist[i + 2], e3 = g_elist[i + 3];
        acc += __half2float(m[(size_t)e0 * HD + c]);
        acc += __half2float(m[(size_t)e1 * HD + c]);
        acc += __half2float(m[(size_t)e2 * HD + c]);
        acc += __half2float(m[(size_t)e3 * HD + c]);
    }
    for (; i < e; i++)
        acc += __half2float(m[(size_t)g_elist[i] * HD + c]);

    const float v = hV[(size_t)n * HD + c] + acc * (1.0f / 30.0f);
    float s1 = v, s2 = v * v;
#pragma unroll
    for (int off = 16; off; off >>= 1) {
        s1 += __shfl_xor_sync(0xffffffffu, s1, off);
        s2 += __shfl_xor_sync(0xffffffffu, s2, off);
    }
    if (lane == 0) { sm1[wid] = s1; sm2[wid] = s2; }
    __syncthreads();
    float t1 = 0.f, t2 = 0.f;
#pragma unroll
    for (int k = 0; k < 8; k++) { t1 += sm1[k]; t2 += sm2[k]; }
    const float mu  = t1 * (1.0f / HD);
    const float var = t2 * (1.0f / HD) - mu * mu;
    const float rs  = rsqrtf(var + 1e-5f);
    const float y = (v - mu) * rs * g1[c] + b1[c];
    h [(size_t)n * HD + c] = y;
    hh[(size_t)n * HD + c] = __float2half(y);
}

// ---------------- GEMM1: fp32 A -> fp16, K=512, 512 thr, 3-stage, hoisted addrs ----------------
__global__ void __launch_bounds__(512, 1)
gemm1_kernel(const float* __restrict__ Af, const __half* __restrict__ WTm0,
             const float* __restrict__ bias, __half* __restrict__ out) {
    constexpr int K = 512;
    extern __shared__ char smem[];
    __half* As = (__half*)smem;
    const int tid = threadIdx.x;
    const int m0  = blockIdx.x * BM;

    const uint32_t sA = (uint32_t)__cvta_generic_to_shared(smem);
    const uint32_t sB = sA + NSTAGE * A_BYTES;

    const int lane = tid & 31, warp = tid >> 5;
    const int wm = warp & 3, wn = warp >> 2;
    const int ml = lane & 7, tl = lane >> 3;

    const uint32_t aW = (uint32_t)(((wm * 32 + ml + (tl & 1) * 8) * ASTR + (tl >> 1) * 8) * 2);
    const uint32_t bW = (uint32_t)(((wn * 64 + ml + (tl >> 1) * 8) * ASTR + (tl & 1) * 8) * 2);

    // hoisted producer state
    const int pr = tid >> 3, pq = tid & 7;
    const float* aLdg = Af + (size_t)(m0 + pr) * K + pq * 8;    // chunk 2: +64*K
    const __half* bLdg = WTm0 + (size_t)pr * K + pq * 8;        // chunks: +i*64*K
    const uint32_t stT = (uint32_t)((pr * ASTR + pq * 8) * 2);  // smem thread offset (bytes)

    float4 ra[2][2];
    auto ldgA = [&]() {
        const float4* p0 = (const float4*)aLdg;
        const float4* p1 = (const float4*)(aLdg + (size_t)64 * K);
        ra[0][0] = p0[0]; ra[0][1] = p0[1];
        ra[1][0] = p1[0]; ra[1][1] = p1[1];
        aLdg += BK;
    };
    auto stsA = [&](int slot) {
        uint32_t d = sA + slot * A_BYTES + stT;
#pragma unroll
        for (int i = 0; i < 2; i++) {
            alignas(16) __half2 hv[4];
            hv[0] = __floats2half2_rn(ra[i][0].x, ra[i][0].y);
            hv[1] = __floats2half2_rn(ra[i][0].z, ra[i][0].w);
            hv[2] = __floats2half2_rn(ra[i][1].x, ra[i][1].y);
            hv[3] = __floats2half2_rn(ra[i][1].z, ra[i][1].w);
            asm volatile("st.shared.v4.b32 [%0], {%1,%2,%3,%4};"
                         :: "r"(d + (uint32_t)(i * 64 * ASTR * 2)),
                            "r"(*(uint32_t*)&hv[0]), "r"(*(uint32_t*)&hv[1]),
                            "r"(*(uint32_t*)&hv[2]), "r"(*(uint32_t*)&hv[3]) : "memory");
        }
    };
    auto issueB = [&](int slot) {
        uint32_t d = sB + slot * B_BYTES + stT;
#pragma unroll
        for (int i = 0; i < 4; i++)
            cpasync16(d + (uint32_t)(i * 64 * ASTR * 2), bLdg + (size_t)i * 64 * K);
        bLdg += BK;
        cp_commit();
    };

    float acc[2][8][4];
#pragma unroll
    for (int mi = 0; mi < 2; mi++)
#pragma unroll
        for (int nj = 0; nj < 8; nj++)
#pragma unroll
            for (int j = 0; j < 4; j++) acc[mi][nj][j] = 0.f;

    const int NC = K / BK;  // 8
    ldgA(); stsA(0); issueB(0);
    ldgA(); stsA(1); issueB(1);
    ldgA();

    for (int c = 0; c < NC; c++) {
        const int slot = c % NSTAGE;
        if (c + 1 < NC) asm volatile("cp.async.wait_group 1;" ::: "memory");
        else            asm volatile("cp.async.wait_group 0;" ::: "memory");
        __syncthreads();
        if (c + 2 < NC) {
            stsA((c + 2) % NSTAGE);
            issueB((c + 2) % NSTAGE);
            if (c + 3 < NC) ldgA();
        }
        mma_chunk(acc, sA + slot * A_BYTES + aW, sB + slot * B_BYTES + bW);
    }

    const int g  = lane >> 2;
    const int t2 = (lane & 3) * 2;
#pragma unroll
    for (int mi = 0; mi < 2; mi++) {
        const int r0 = wm * 32 + mi * 16 + g;
#pragma unroll
        for (int nj = 0; nj < 8; nj++) {
            const int col = wn * 64 + nj * 8 + t2;
            const float b0v = bias[col], b1v = bias[col + 1];
            float x0 = gelu_f(acc[mi][nj][0] + b0v);
            float x1 = gelu_f(acc[mi][nj][1] + b1v);
            *(__half2*)(out + (size_t)(m0 + r0) * HD + col) = __floats2half2_rn(x0, x1);
            float x2 = gelu_f(acc[mi][nj][2] + b0v);
            float x3 = gelu_f(acc[mi][nj][3] + b1v);
            *(__half2*)(out + (size_t)(m0 + r0 + 8) * HD + col) = __floats2half2_rn(x2, x3);
        }
    }
}

// ---------------- fused edge GEMM2+GEMM3 (hoisted addrs) ----------------
__global__ void __launch_bounds__(512, 1)
gemm_fused23(const __half* __restrict__ Xin,
             const __half* __restrict__ W1, const float* __restrict__ b1,
             const __half* __restrict__ W2, const float* __restrict__ b2,
             __half* __restrict__ out) {
    extern __shared__ char smem[];
    __half* As2 = (__half*)smem;
    const int tid = threadIdx.x;
    const int m0  = blockIdx.x * BM;

    const uint32_t sA  = (uint32_t)__cvta_generic_to_shared(smem);
    const uint32_t sB  = sA + NSTAGE * A_BYTES;
    const uint32_t sA2 = sA + A2_OFF;
    const uint32_t sB2 = sA + B2_OFF;

    const int lane = tid & 31, warp = tid >> 5;
    const int wm = warp & 3, wn = warp >> 2;
    const int ml = lane & 7, tl = lane >> 3;

    const uint32_t aW = (uint32_t)(((wm * 32 + ml + (tl & 1) * 8) * ASTR + (tl >> 1) * 8) * 2);
    const uint32_t bW = (uint32_t)(((wn * 64 + ml + (tl >> 1) * 8) * ASTR + (tl & 1) * 8) * 2);

    const int pr = tid >> 3, pq = tid & 7;
    const uint32_t stT = (uint32_t)((pr * ASTR + pq * 8) * 2);
    const __half* xLdg  = Xin + (size_t)(m0 + pr) * 256 + pq * 8;
    const __half* w1Ldg = W1 + (size_t)pr * 256 + pq * 8;
    const __half* w2Ldg = W2 + (size_t)pr * 256 + pq * 8;

    auto issue1 = [&](int slot) {
        uint32_t dA = sA + slot * A_BYTES + stT;
        uint32_t dB = sB + slot * B_BYTES + stT;
        cpasync16(dA, xLdg);
        cpasync16(dA + (uint32_t)(64 * ASTR * 2), xLdg + (size_t)64 * 256);
#pragma unroll
        for (int i = 0; i < 4; i++)
            cpasync16(dB + (uint32_t)(i * 64 * ASTR * 2), w1Ldg + (size_t)i * 64 * 256);
        xLdg += BK; w1Ldg += BK;
        cp_commit();
    };
    auto issue2 = [&](int slot) {
        uint32_t dB = sB2 + slot * B_BYTES + stT;
#pragma unroll
        for (int i = 0; i < 4; i++)
            cpasync16(dB + (uint32_t)(i * 64 * ASTR * 2), w2Ldg + (size_t)i * 64 * 256);
        w2Ldg += BK;
        cp_commit();
    };

    float acc[2][8][4];
#pragma unroll
    for (int mi = 0; mi < 2; mi++)
#pragma unroll
        for (int nj = 0; nj < 8; nj++)
#pragma unroll
            for (int j = 0; j < 4; j++) acc[mi][nj][j] = 0.f;

    issue1(0);
    issue1(1);
    for (int c = 0; c < 4; c++) {
        const int slot = c % NSTAGE;
        if (c + 1 < 4) asm volatile("cp.async.wait_group 1;" ::: "memory");
        else           asm volatile("cp.async.wait_group 0;" ::: "memory");
        __syncthreads();
        if (c + 2 < 4) issue1((c + 2) % NSTAGE);
        mma_chunk(acc, sA + slot * A_BYTES + aW, sB + slot * B_BYTES + bW);
    }

    __syncthreads();
    issue2(0);
    issue2(1);
    {
        const int g  = lane >> 2;
        const int t2 = (lane & 3) * 2;
#pragma unroll
        for (int mi = 0; mi < 2; mi++) {
            const int r0 = wm * 32 + mi * 16 + g;
#pragma unroll
            for (int nj = 0; nj < 8; nj++) {
                const int cl  = nj * 8 + t2;
                const int col = wn * 64 + cl;
                const float b0v = b1[col], b1v = b1[col + 1];
                __half2 v01 = __floats2half2_rn(gelu_f(acc[mi][nj][0] + b0v),
                                                gelu_f(acc[mi][nj][1] + b1v));
                __half2 v23 = __floats2half2_rn(gelu_f(acc[mi][nj][2] + b0v),
                                                gelu_f(acc[mi][nj][3] + b1v));
                *(__half2*)(As2 + wn * (A_BYTES / 2) + r0 * ASTR + cl)       = v01;
                *(__half2*)(As2 + wn * (A_BYTES / 2) + (r0 + 8) * ASTR + cl) = v23;
                acc[mi][nj][0] = acc[mi][nj][1] = acc[mi][nj][2] = acc[mi][nj][3] = 0.f;
            }
        }
    }
    __syncthreads();

    for (int c = 0; c < 4; c++) {
        const int slot = c & 1;
        if (c + 1 < 4) asm volatile("cp.async.wait_group 1;" ::: "memory");
        else           asm volatile("cp.async.wait_group 0;" ::: "memory");
        __syncthreads();
        mma_chunk(acc, sA2 + c * A_BYTES + aW, sB2 + slot * B_BYTES + bW);
        __syncthreads();
        if (c + 2 < 4) issue2(slot);
    }

    {
        const int g  = lane >> 2;
        const int t2 = (lane & 3) * 2;
#pragma unroll
        for (int mi = 0; mi < 2; mi++) {
            const int r0 = wm * 32 + mi * 16 + g;
#pragma unroll
            for (int nj = 0; nj < 8; nj++) {
                const int col = wn * 64 + nj * 8 + t2;
                const float b0v = b2[col], b1v = b2[col + 1];
                float x0 = gelu_f(acc[mi][nj][0] + b0v);
                float x1 = gelu_f(acc[mi][nj][1] + b1v);
                *(__half2*)(out + (size_t)(m0 + r0) * HD + col) = __floats2half2_rn(x0, x1);
                float x2 = gelu_f(acc[mi][nj][2] + b0v);
                float x3 = gelu_f(acc[mi][nj][3] + b1v);
                *(__half2*)(out + (size_t)(m0 + r0 + 8) * HD + col) = __floats2half2_rn(x2, x3);
            }
        }
    }
}

// ---------------- gemm64: BM=64, BN=256, 512 thr, 2-stage, 2 CTAs/SM ----------------
template <int K, int EPI>
__global__ void __launch_bounds__(512, 2)
gemm64(const __half* __restrict__ Ah, const __half* __restrict__ WT_full,
       const float* __restrict__ bias_full,
       __half* __restrict__ out, int ldout,
       const float* __restrict__ h_res, const float* __restrict__ ln_g,
       const float* __restrict__ ln_b, float* __restrict__ outf) {
    extern __shared__ char smem[];
    const int tid = threadIdx.x;
    const int m0  = blockIdx.x * BM64;
    const int n0g = blockIdx.y * BN;
    const __half* WT  = WT_full + (size_t)n0g * K;
    const float* bias = bias_full + n0g;

    const uint32_t sA = (uint32_t)__cvta_generic_to_shared(smem);
    const uint32_t sB = sA + 2 * A64_BYTES;

    const int lane = tid & 31, warp = tid >> 5;
    const int wm = warp & 3, wn = warp >> 2;      // 4 m-warps (16 rows) x 4 n-warps (64 cols)
    const int ml = lane & 7, tl = lane >> 3;

    const uint32_t aW = (uint32_t)(((wm * 16 + ml + (tl & 1) * 8) * ASTR + (tl >> 1) * 8) * 2);
    const uint32_t bW = (uint32_t)(((wn * 64 + ml + (tl >> 1) * 8) * ASTR + (tl & 1) * 8) * 2);

    const int pr = tid >> 3, pq = tid & 7;
    const uint32_t stT = (uint32_t)((pr * ASTR + pq * 8) * 2);
    const __half* aLdg = Ah + (size_t)(m0 + pr) * K + pq * 8;
    const __half* bLdg = WT + (size_t)pr * K + pq * 8;

    auto issue = [&](int slot) {
        cpasync16(sA + slot * A64_BYTES + stT, aLdg);
        uint32_t dB = sB + slot * B_BYTES + stT;
#pragma unroll
        for (int i = 0; i < 4; i++)
            cpasync16(dB + (uint32_t)(i * 64 * ASTR * 2), bLdg + (size_t)i * 64 * K);
        aLdg += BK; bLdg += BK;
        cp_commit();
    };

    float acc[8][4];
#pragma unroll
    for (int nj = 0; nj < 8; nj++)
#pragma unroll
        for (int j = 0; j < 4; j++) acc[nj][j] = 0.f;

    const int NC = K / BK;
    issue(0);
    issue(1);
    for (int c = 0; c < NC; c++) {
        const int slot = c & 1;
        if (c + 1 < NC) asm volatile("cp.async.wait_group 1;" ::: "memory");
        else            asm volatile("cp.async.wait_group 0;" ::: "memory");
        __syncthreads();

        const uint32_t aS = sA + slot * A64_BYTES + aW;
        const uint32_t bS = sB + slot * B_BYTES + bW;
#pragma unroll
        for (int ks = 0; ks < 4; ks++) {
            const uint32_t kb = (uint32_t)(ks * 16 * 2);
            uint32_t afr[4];
            ldsm4(afr, aS + kb);
#pragma unroll
            for (int jj = 0; jj < 4; jj++) {
                uint32_t bfr[4];
                ldsm4(bfr, bS + kb + (uint32_t)(jj * 16 * ASTR * 2));
                mma16816(acc[2 * jj],     afr, bfr);
                mma16816(acc[2 * jj + 1], afr, bfr + 2);
            }
        }
        __syncthreads();
        if (c + 2 < NC) issue(slot);
    }

    const int g  = lane >> 2;
    const int t2 = (lane & 3) * 2;

    if constexpr (EPI == EPI_GELU) {
        const int r0 = wm * 16 + g;
#pragma unroll
        for (int nj = 0; nj < 8; nj++) {
            const int col = wn * 64 + nj * 8 + t2;
            const float b0v = bias[col], b1v = bias[col + 1];
            float x0 = gelu_f(acc[nj][0] + b0v);
            float x1 = gelu_f(acc[nj][1] + b1v);
            *(__half2*)(out + (size_t)(m0 + r0) * ldout + n0g + col) = __floats2half2_rn(x0, x1);
            float x2 = gelu_f(acc[nj][2] + b0v);
            float x3 = gelu_f(acc[nj][3] + b1v);
            *(__half2*)(out + (size_t)(m0 + r0 + 8) * ldout + n0g + col) = __floats2half2_rn(x2, x3);
        }
    } else {  // EPI_LN2
        __syncthreads();
        float* sb = (float*)smem;   // [64][264] = 67584 B <= 92160
        {
            const int r0 = wm * 16 + g;
#pragma unroll
            for (int nj = 0; nj < 8; nj++) {
                const int col = wn * 64 + nj * 8 + t2;
                const float b0v = bias[col], b1v = bias[col + 1];
                sb[r0 * 264 + col]           = acc[nj][0] + b0v + h_res[(size_t)(m0 + r0) * HD + col];
                sb[r0 * 264 + col + 1]       = acc[nj][1] + b1v + h_res[(size_t)(m0 + r0) * HD + col + 1];
                sb[(r0 + 8) * 264 + col]     = acc[nj][2] + b0v + h_res[(size_t)(m0 + r0 + 8) * HD + col];
                sb[(r0 + 8) * 264 + col + 1] = acc[nj][3] + b1v + h_res[(size_t)(m0 + r0 + 8) * HD + col + 1];
            }
        }
        __syncthreads();
        for (int rr = 0; rr < 4; rr++) {
            const int row = warp * 4 + rr;
            float s = 0.f, s2 = 0.f;
#pragma unroll
            for (int i = 0; i < 8; i++) {
                float v = sb[row * 264 + lane + i * 32];
                s += v; s2 += v * v;
            }
#pragma unroll
            for (int off = 16; off; off >>= 1) {
                s  += __shfl_xor_sync(0xffffffffu, s, off);
                s2 += __shfl_xor_sync(0xffffffffu, s2, off);
            }
            const float mu  = s * (1.0f / HD);
            const float var = s2 * (1.0f / HD) - mu * mu;
            const float rs  = rsqrtf(var + 1e-5f);
#pragma unroll
            for (int i = 0; i < 8; i++) {
                const int cc = lane + i * 32;
                const float v = sb[row * 264 + cc];
                outf[(size_t)(m0 + row) * HD + cc] = (v - mu) * rs * ln_g[cc] + ln_b[cc];
            }
        }
    }
}

// ---------------- host launcher ----------------
extern "C" void kernel_launch(void* const* d_in, const int* in_sizes, int n_in,
                              void* d_out, int out_size) {
    const float* h_V  = (const float*)d_in[0];
    const float* h_E  = (const float*)d_in[1];
    const void*  eidx = d_in[2];
    const float* m0w  = (const float*)d_in[3];
    const float* m0b  = (const float*)d_in[4];
    const float* m1w  = (const float*)d_in[5];
    const float* m1b  = (const float*)d_in[6];
    const float* m2w  = (const float*)d_in[7];
    const float* m2b  = (const float*)d_in[8];
    const float* d0w  = (const float*)d_in[9];
    const float* d0b  = (const float*)d_in[10];
    const float* d1w  = (const float*)d_in[11];
    const float* d1b  = (const float*)d_in[12];
    const float* d2w  = (const float*)d_in[13];
    const float* d2b  = (const float*)d_in[14];
    const float* ln1g = (const float*)d_in[15];
    const float* ln1b = (const float*)d_in[16];
    const float* ln2g = (const float*)d_in[17];
    const float* ln2b = (const float*)d_in[18];
    float* outf = (float*)d_out;
    (void)n_in; (void)out_size; (void)in_sizes;

    void *pWT, *pXa, *pXb, *pH, *pHH;
    cudaGetSymbolAddress(&pWT, g_WT);
    cudaGetSymbolAddress(&pXa, g_Xa);
    cudaGetSymbolAddress(&pXb, g_Xb);
    cudaGetSymbolAddress(&pH,  g_h);
    cudaGetSymbolAddress(&pHH, g_hh);
    __half* WT = (__half*)pWT;
    __half* Xa = (__half*)pXa;
    __half* Xb = (__half*)pXb;
    float*  hb = (float*)pH;
    __half* hh = (__half*)pHH;

    cudaFuncSetAttribute(gemm1_kernel, cudaFuncAttributeMaxDynamicSharedMemorySize, SMEM_MMA);
    cudaFuncSetAttribute(gemm_fused23, cudaFuncAttributeMaxDynamicSharedMemorySize, SMEM_MMA);
    cudaFuncSetAttribute(gemm64<256,  EPI_GELU>, cudaFuncAttributeMaxDynamicSharedMemorySize, SMEM64);
    cudaFuncSetAttribute(gemm64<1024, EPI_GELU>, cudaFuncAttributeMaxDynamicSharedMemorySize, SMEM64);
    cudaFuncSetAttribute(gemm64<1024, EPI_LN2>,  cudaFuncAttributeMaxDynamicSharedMemorySize, SMEM64);

    // --- launch order: GEMM1 is the 4th launch (ncu capture slot) ---
    detect_idx_kernel<<<1, 32>>>((const int*)eidx);                                // 1
    prep_all_kernel<<<1835008 / 256, 256>>>(m0w, m1w, m2w, d0w, d1w, d2w, WT);     // 2
    zero_cnt_kernel<<<NNODES / 256, 256>>>();                                      // 3
    gemm1_kernel<<<EDGES / BM, 512, SMEM_MMA>>>(h_E, WT + WOFF_M0, m0b, Xa);       // 4 <- profiled

    gemm_fused23<<<EDGES / BM, 512, SMEM_MMA>>>(
        Xa, WT + WOFF_M1, m1b, WT + WOFF_M2, m2b, Xa);

    count_kernel<<<EDGES / 256, 256>>>(eidx);
    scan_kernel<<<1, 1024>>>();
    fill_kernel<<<EDGES / 256, 256>>>(eidx);

    gather_ln1_kernel<<<NNODES, 256>>>(Xa, h_V, ln1g, ln1b, hb, hh);

    // --- dense MLP (BM=64, 2 CTAs/SM) ---
    gemm64<256, EPI_GELU><<<dim3(NNODES / BM64, 4), 512, SMEM64>>>(
        hh, WT + WOFF_D0, d0b, Xb, DD, nullptr, nullptr, nullptr, nullptr);
    gemm64<1024, EPI_GELU><<<dim3(NNODES / BM64, 4), 512, SMEM64>>>(
        Xb, WT + WOFF_D1, d1b, Xa, DD, nullptr, nullptr, nullptr, nullptr);
    gemm64<1024, EPI_LN2><<<dim3(NNODES / BM64, 1), 512, SMEM64>>>(
        Xa, WT + WOFF_D2, d2b, nullptr, 0, hb, ln2g, ln2b, outf);
}